// round 1
// baseline (speedup 1.0000x reference)
#include <cuda_runtime.h>
#include <math.h>

#define Bdim 16
#define Tdim 1024
#define Cdim 512
#define Kma  25
#define NWv  4
#define Mrows (Bdim*Tdim)   // 16384
#define SEG  8
#define SEGLEN (Tdim/SEG)   // 128

// ---------------- scratch (static device allocations are allowed) ----------
__device__ float g_xt  [Mrows*Cdim];     // tanh(trend_ctx)
__device__ float g_sctx[Mrows*Cdim];     // spike_ctx
__device__ float g_tout[Mrows*Cdim];     // trend_out
__device__ float g_sout[Mrows*Cdim];     // spike_out pre-gate
__device__ float g_amp [Mrows*Cdim];     // amp_scale
__device__ float g_Wc  [3*Cdim*Cdim];    // cheby rearranged [(d-1,c), o]
__device__ float g_bias0[Cdim];          // sum_c cheby[c,o,0]
__device__ float g_psi [Mrows*NWv];
__device__ float g_Spart[SEG][Bdim*Cdim];
__device__ float g_tr0[Bdim*Cdim];
__device__ float g_trN[Bdim*Cdim];

// ---------------- K0a: bias0[o] = sum_c cheby[c,o,0] ------------------------
__global__ void bias0_kernel(const float* __restrict__ cheby) {
    int o = threadIdx.x;
    float s = 0.f;
    for (int c = 0; c < Cdim; ++c) s += cheby[(c*Cdim + o)*4];
    g_bias0[o] = s;
}

// ---------------- K0b: Wc[(d-1)*512+c][o] = cheby[c,o,d], d=1..3 ------------
__global__ void transpose_kernel(const float* __restrict__ cheby) {
    int i = blockIdx.x*blockDim.x + threadIdx.x;
    if (i >= Cdim*Cdim) return;
    int c = i >> 9, o = i & 511;
    float4 v = reinterpret_cast<const float4*>(cheby)[i];  // (c*512+o)*4 + {0..3}
    g_Wc[(0*Cdim + c)*Cdim + o] = v.y;
    g_Wc[(1*Cdim + c)*Cdim + o] = v.z;
    g_Wc[(2*Cdim + c)*Cdim + o] = v.w;
}

// ---------------- K1: fused decomposition ----------------------------------
// per (seg,b,c): causal MA(25) via running window, spike split, dwconv3 on
// trend (->tanh->g_xt) and spike (->g_sctx), pooling stats.
__global__ void decomp_kernel(const float* __restrict__ x,
                              const float* __restrict__ tw, const float* __restrict__ tb,
                              const float* __restrict__ sw, const float* __restrict__ sb) {
    int idx = blockIdx.x*blockDim.x + threadIdx.x;          // 65536 threads
    int c   = idx & (Cdim-1);
    int tmp = idx >> 9;
    int b   = tmp & (Bdim-1);
    int seg = tmp >> 4;
    const float* xb = x + (size_t)b*Tdim*Cdim + c;
    const float inv = 1.0f/(float)Kma;
    float w0t=tw[c*3+0], w1t=tw[c*3+1], w2t=tw[c*3+2], btc=tb[c];
    float w0s=sw[c*3+0], w1s=sw[c*3+1], w2s=sw[c*3+2], bsc=sb[c];

    int t0 = seg*SEGLEN, t1 = t0 + SEGLEN;
    float ws = 0.f;
    int tref = (seg==0) ? 0 : (t0-1);
    #pragma unroll 5
    for (int j = tref-(Kma-1); j <= tref; ++j) ws += xb[max(j,0)*Cdim];

    float tr_m1, tr_c, x_m1, x_c;
    if (seg == 0) {
        tr_c = ws*inv; tr_m1 = tr_c;
        x_c  = xb[0];  x_m1  = x_c;
    } else {
        tr_m1 = ws*inv;
        x_m1  = xb[(t0-1)*Cdim];
        ws   += xb[t0*Cdim] - xb[max(t0-Kma,0)*Cdim];
        tr_c  = ws*inv;
        x_c   = xb[t0*Cdim];
    }

    float Ssum = 0.f;
    #pragma unroll 4
    for (int t = t0; t < t1; ++t) {
        Ssum += tr_c;
        float tr_p, x_p;
        if (t+1 < Tdim) {
            x_p = xb[(t+1)*Cdim];
            ws += x_p - xb[max(t+1-Kma,0)*Cdim];
            tr_p = ws*inv;
        } else { x_p = x_c; tr_p = tr_c; }

        int o = (b*Tdim + t)*Cdim + c;
        float tctx = fmaf(tr_m1,w0t, fmaf(tr_c,w1t, fmaf(tr_p,w2t, btc)));
        g_xt[o] = tanhf(tctx);
        float sm1 = x_m1-tr_m1, sc = x_c-tr_c, spp = x_p-tr_p;
        g_sctx[o] = fmaf(sm1,w0s, fmaf(sc,w1s, fmaf(spp,w2s, bsc)));

        if (t == 0)      g_tr0[b*Cdim+c] = tr_c;
        if (t == Tdim-1) g_trN[b*Cdim+c] = tr_c;
        tr_m1 = tr_c; tr_c = tr_p; x_m1 = x_c; x_c = x_p;
    }
    g_Spart[seg][b*Cdim+c] = Ssum;
}

// ---------------- K2: hypernetwork + psi ------------------------------------
__global__ void hyper_kernel(const float* __restrict__ slw, const float* __restrict__ slb,
                             const float* __restrict__ w1,  const float* __restrict__ b1,
                             const float* __restrict__ w2,  const float* __restrict__ b2) {
    int b = blockIdx.x;
    int j = threadIdx.x;                 // 512 threads
    __shared__ float h[2*Cdim];
    __shared__ float h1[Cdim];
    __shared__ float params_s[2*NWv];
    __shared__ float da[NWv], db[NWv];

    // pooled stats -> h
    {
        int c = j;
        float S = 0.f;
        #pragma unroll
        for (int s = 0; s < SEG; ++s) S += g_Spart[s][b*Cdim+c];
        float tr0 = g_tr0[b*Cdim+c], trN = g_trN[b*Cdim+c];
        float a0 = slw[c*3+0], a1 = slw[c*3+1], a2 = slw[c*3+2];
        float sp = (a0*(S + tr0 - trN) + a1*S + a2*(S - tr0 + trN)) * (1.0f/Tdim) + slb[c];
        h[c]        = sp;
        h[Cdim + c] = S * (1.0f/Tdim);
    }
    __syncthreads();

    // h1 = silu(h @ W1 + b1)
    {
        float acc = b1[j];
        for (int i = 0; i < 2*Cdim; ++i) acc = fmaf(h[i], w1[i*Cdim + j], acc);
        h1[j] = acc / (1.f + expf(-acc));
    }
    __syncthreads();

    // params = h1 @ W2 + b2 (8 outputs); first 8 warps each reduce one
    {
        int warp = j >> 5, lane = j & 31;
        if (warp < 2*NWv) {
            float v = 0.f;
            for (int jj = lane; jj < Cdim; jj += 32) v = fmaf(h1[jj], w2[jj*(2*NWv) + warp], v);
            #pragma unroll
            for (int o = 16; o; o >>= 1) v += __shfl_down_sync(0xffffffffu, v, o);
            if (lane == 0) params_s[warp] = v + b2[warp];
        }
    }
    __syncthreads();
    if (j < NWv) {
        float a = params_s[j*2+0], bb = params_s[j*2+1];
        da[j] = ((a > 20.f) ? a : log1pf(expf(a))) + 0.01f;
        db[j] = (float)Tdim / (1.f + expf(-bb));
    }
    __syncthreads();

    // psi[b,t,w]
    for (int t = j; t < Tdim; t += blockDim.x) {
        #pragma unroll
        for (int w = 0; w < NWv; ++w) {
            float z  = ((float)t - db[w]) / da[w];
            float z2 = z*z;
            g_psi[(b*Tdim + t)*NWv + w] = (1.f - z2) * expf(-0.5f*z2);
        }
    }
}

// ---------------- K3: templated GEMM ----------------------------------------
// MODE 0: trend_out = basis(g_xt) @ g_Wc + bias0        (Ktot=1536, k=(d-1,c))
// MODE 1: spike_out = (psi (x) g_sctx) @ wavelet_w      (Ktot=2048, k=(w,c))
// MODE 2: amp = 2*sigmoid(trend_out @ amp_w + amp_b)    (Ktot=512)
#define BM 128
#define BN 64
#define BK 16

template<int MODE>
__global__ __launch_bounds__(256)
void gemm_kernel(const float* __restrict__ Bext, const float* __restrict__ biasv, int Ktot) {
    const float* Asrc = (MODE==0) ? g_xt : (MODE==1) ? g_sctx : g_tout;
    const float* Bmat = (MODE==0) ? g_Wc : Bext;
    float*       Cout = (MODE==0) ? g_tout : (MODE==1) ? g_sout : g_amp;

    __shared__ float As[BK][BM];
    __shared__ float Bs[BK][BN];

    int m0 = blockIdx.y * BM;
    int n0 = blockIdx.x * BN;
    int tid = threadIdx.x;
    int tx = tid & 15, ty = tid >> 4;

    float acc[8][4];
    #pragma unroll
    for (int i = 0; i < 8; ++i)
        #pragma unroll
        for (int jj = 0; jj < 4; ++jj) acc[i][jj] = 0.f;

    int ar  = tid >> 2;         // 0..63 (A row within pass)
    int ac4 = (tid & 3) * 4;    // 0,4,8,12
    int br  = tid >> 4;         // 0..15
    int bc  = (tid & 15) * 4;   // 0..60

    for (int k0 = 0; k0 < Ktot; k0 += BK) {
        int sub = k0 >> 9;      // degree-1 (MODE0) / wavelet idx (MODE1)
        int cb  = k0 & 511;

        #pragma unroll
        for (int p = 0; p < 2; ++p) {
            int r = ar + p*64;
            float4 v = *reinterpret_cast<const float4*>(&Asrc[(size_t)(m0+r)*Cdim + cb + ac4]);
            float4 a = v;
            if (MODE == 0) {
                if (sub == 1) {          // 2x^2 - 1
                    a.x = fmaf(2.f*v.x, v.x, -1.f); a.y = fmaf(2.f*v.y, v.y, -1.f);
                    a.z = fmaf(2.f*v.z, v.z, -1.f); a.w = fmaf(2.f*v.w, v.w, -1.f);
                } else if (sub == 2) {   // x(4x^2 - 3)
                    a.x = v.x*fmaf(4.f*v.x, v.x, -3.f); a.y = v.y*fmaf(4.f*v.y, v.y, -3.f);
                    a.z = v.z*fmaf(4.f*v.z, v.z, -3.f); a.w = v.w*fmaf(4.f*v.w, v.w, -3.f);
                }
            } else if (MODE == 1) {
                float pw = g_psi[(m0+r)*NWv + sub];
                a.x = v.x*pw; a.y = v.y*pw; a.z = v.z*pw; a.w = v.w*pw;
            }
            As[ac4+0][r] = a.x; As[ac4+1][r] = a.y;
            As[ac4+2][r] = a.z; As[ac4+3][r] = a.w;
        }
        *reinterpret_cast<float4*>(&Bs[br][bc]) =
            *reinterpret_cast<const float4*>(&Bmat[(size_t)(k0+br)*Cdim + n0 + bc]);
        __syncthreads();

        #pragma unroll
        for (int kk = 0; kk < BK; ++kk) {
            float4 A0 = *reinterpret_cast<float4*>(&As[kk][ty*8]);
            float4 A1 = *reinterpret_cast<float4*>(&As[kk][ty*8+4]);
            float4 B0 = *reinterpret_cast<float4*>(&Bs[kk][tx*4]);
            float a_[8] = {A0.x,A0.y,A0.z,A0.w,A1.x,A1.y,A1.z,A1.w};
            float b_[4] = {B0.x,B0.y,B0.z,B0.w};
            #pragma unroll
            for (int i = 0; i < 8; ++i)
                #pragma unroll
                for (int jj = 0; jj < 4; ++jj)
                    acc[i][jj] = fmaf(a_[i], b_[jj], acc[i][jj]);
        }
        __syncthreads();
    }

    int nb = n0 + tx*4;
    #pragma unroll
    for (int i = 0; i < 8; ++i) {
        int row = m0 + ty*8 + i;
        float4 o4;
        o4.x = acc[i][0]; o4.y = acc[i][1]; o4.z = acc[i][2]; o4.w = acc[i][3];
        if (MODE == 0) {
            o4.x += g_bias0[nb+0]; o4.y += g_bias0[nb+1];
            o4.z += g_bias0[nb+2]; o4.w += g_bias0[nb+3];
        } else if (MODE == 2) {
            o4.x = 2.f/(1.f+expf(-(o4.x + biasv[nb+0])));
            o4.y = 2.f/(1.f+expf(-(o4.y + biasv[nb+1])));
            o4.z = 2.f/(1.f+expf(-(o4.z + biasv[nb+2])));
            o4.w = 2.f/(1.f+expf(-(o4.w + biasv[nb+3])));
        }
        *reinterpret_cast<float4*>(&Cout[(size_t)row*Cdim + nb]) = o4;
    }
}

// ---------------- K5: gate + residual + LayerNorm ---------------------------
__global__ void epilogue_kernel(const float* __restrict__ x,
                                const float* __restrict__ gamma,
                                const float* __restrict__ beta,
                                float* __restrict__ out) {
    int m = blockIdx.x;
    int i = threadIdx.x;            // 128 threads, 4 floats each
    size_t base = (size_t)m*Cdim + i*4;
    float4 to = *reinterpret_cast<const float4*>(&g_tout[base]);
    float4 sp = *reinterpret_cast<const float4*>(&g_sout[base]);
    float4 am = *reinterpret_cast<const float4*>(&g_amp[base]);
    float4 xv = *reinterpret_cast<const float4*>(&x[base]);
    float4 y;
    y.x = fmaf(sp.x, am.x, to.x) + xv.x;
    y.y = fmaf(sp.y, am.y, to.y) + xv.y;
    y.z = fmaf(sp.z, am.z, to.z) + xv.z;
    y.w = fmaf(sp.w, am.w, to.w) + xv.w;

    float s  = y.x + y.y + y.z + y.w;
    float sq = y.x*y.x + y.y*y.y + y.z*y.z + y.w*y.w;
    #pragma unroll
    for (int o = 16; o; o >>= 1) {
        s  += __shfl_down_sync(0xffffffffu, s,  o);
        sq += __shfl_down_sync(0xffffffffu, sq, o);
    }
    __shared__ float rs[4], rq[4];
    int warp = i >> 5, lane = i & 31;
    if (lane == 0) { rs[warp] = s; rq[warp] = sq; }
    __syncthreads();
    float ts = rs[0]+rs[1]+rs[2]+rs[3];
    float tq = rq[0]+rq[1]+rq[2]+rq[3];
    float mu  = ts * (1.0f/Cdim);
    float var = tq * (1.0f/Cdim) - mu*mu;
    float r = rsqrtf(var + 1e-5f);

    float4 g = *reinterpret_cast<const float4*>(&gamma[i*4]);
    float4 bb= *reinterpret_cast<const float4*>(&beta[i*4]);
    float4 o4;
    o4.x = (y.x-mu)*r*g.x + bb.x;
    o4.y = (y.y-mu)*r*g.y + bb.y;
    o4.z = (y.z-mu)*r*g.z + bb.z;
    o4.w = (y.w-mu)*r*g.w + bb.w;
    *reinterpret_cast<float4*>(&out[base]) = o4;
}

// ---------------- launch -----------------------------------------------------
extern "C" void kernel_launch(void* const* d_in, const int* in_sizes, int n_in,
                              void* d_out, int out_size) {
    const float* x     = (const float*)d_in[0];
    const float* tw    = (const float*)d_in[1];
    const float* tb    = (const float*)d_in[2];
    const float* sw    = (const float*)d_in[3];
    const float* sb    = (const float*)d_in[4];
    const float* slw   = (const float*)d_in[5];
    const float* slb   = (const float*)d_in[6];
    const float* cheby = (const float*)d_in[7];
    const float* hw1   = (const float*)d_in[8];
    const float* hb1   = (const float*)d_in[9];
    const float* hw2   = (const float*)d_in[10];
    const float* hb2   = (const float*)d_in[11];
    const float* amp_w = (const float*)d_in[12];
    const float* amp_b = (const float*)d_in[13];
    const float* wav_w = (const float*)d_in[14];
    const float* gamma = (const float*)d_in[15];
    const float* beta  = (const float*)d_in[16];
    float* out = (float*)d_out;

    bias0_kernel<<<1, 512>>>(cheby);
    transpose_kernel<<<(Cdim*Cdim+255)/256, 256>>>(cheby);
    decomp_kernel<<<(SEG*Bdim*Cdim)/256, 256>>>(x, tw, tb, sw, sb);
    hyper_kernel<<<Bdim, 512>>>(slw, slb, hw1, hb1, hw2, hb2);

    dim3 grid(Cdim/BN, Mrows/BM);   // (8, 128)
    gemm_kernel<0><<<grid, 256>>>(nullptr, nullptr, 3*Cdim);   // cheby, K=1536
    gemm_kernel<1><<<grid, 256>>>(wav_w, nullptr, NWv*Cdim);   // wavelet, K=2048
    gemm_kernel<2><<<grid, 256>>>(amp_w, amp_b, Cdim);         // amp, K=512

    epilogue_kernel<<<Mrows, 128>>>(x, gamma, beta, out);
}

// round 3
// speedup vs baseline: 1.8456x; 1.8456x over previous
#include <cuda_runtime.h>
#include <cuda_bf16.h>
#include <cstdint>
#include <math.h>

#define Bdim 16
#define Tdim 1024
#define Cdim 512
#define Kma  25
#define NWv  4
#define Mrows (Bdim*Tdim)   // 16384
#define SEG  8
#define SEGLEN (Tdim/SEG)   // 128

// ===================== scratch ==============================================
__device__ float g_xt  [Mrows*Cdim];
__device__ float g_sctx[Mrows*Cdim];
__device__ float g_tout[Mrows*Cdim];
__device__ float g_sout[Mrows*Cdim];
__device__ float g_amp [Mrows*Cdim];
__device__ float g_bias0[Cdim];
__device__ float g_psi [Mrows*NWv];
__device__ float g_Spart[SEG][Bdim*Cdim];
__device__ float g_tr0[Bdim*Cdim];
__device__ float g_trN[Bdim*Cdim];
// weights transposed to [o][k], split bf16 hi/lo
__device__ __nv_bfloat16 g_Wc_hi[Cdim*3*Cdim], g_Wc_lo[Cdim*3*Cdim];     // Ktot=1536
__device__ __nv_bfloat16 g_Ww_hi[Cdim*NWv*Cdim], g_Ww_lo[Cdim*NWv*Cdim]; // Ktot=2048
__device__ __nv_bfloat16 g_Wa_hi[Cdim*Cdim], g_Wa_lo[Cdim*Cdim];         // Ktot=512

// ===================== K0a: bias0 ===========================================
__global__ void bias0_kernel(const float* __restrict__ cheby) {
    int o = threadIdx.x;
    float s = 0.f;
    for (int c = 0; c < Cdim; ++c) s += cheby[(c*Cdim + o)*4];
    g_bias0[o] = s;
}

// ===================== K0b: weight transpose + bf16 split ===================
template<int MODE>
__global__ void prepW_kernel(const float* __restrict__ src) {
    __nv_bfloat16* hi = (MODE==0) ? g_Wc_hi : (MODE==1) ? g_Ww_hi : g_Wa_hi;
    __nv_bfloat16* lo = (MODE==0) ? g_Wc_lo : (MODE==1) ? g_Ww_lo : g_Wa_lo;
    const int Ktot = (MODE==0) ? 3*Cdim : (MODE==1) ? NWv*Cdim : Cdim;
    __shared__ float tile[32][33];
    int kb = blockIdx.x*32, ob = blockIdx.y*32;
    int tx = threadIdx.x, ty = threadIdx.y;   // 32 x 8
    #pragma unroll
    for (int s = 0; s < 32; s += 8) {
        int k = kb + ty + s, o = ob + tx;
        float v;
        if (MODE == 0) { int d = k >> 9, c = k & 511; v = src[(c*Cdim + o)*4 + d + 1]; }
        else           { v = src[(size_t)k*Cdim + o]; }
        tile[ty+s][tx] = v;
    }
    __syncthreads();
    #pragma unroll
    for (int s = 0; s < 32; s += 8) {
        int o = ob + ty + s, k = kb + tx;
        float v = tile[tx][ty+s];
        __nv_bfloat16 h = __float2bfloat16(v);
        hi[(size_t)o*Ktot + k] = h;
        lo[(size_t)o*Ktot + k] = __float2bfloat16(v - __bfloat162float(h));
    }
}

// ===================== K1: fused decomposition ==============================
__global__ void decomp_kernel(const float* __restrict__ x,
                              const float* __restrict__ tw, const float* __restrict__ tb,
                              const float* __restrict__ sw, const float* __restrict__ sb) {
    int idx = blockIdx.x*blockDim.x + threadIdx.x;
    int c   = idx & (Cdim-1);
    int tmp = idx >> 9;
    int b   = tmp & (Bdim-1);
    int seg = tmp >> 4;
    const float* xb = x + (size_t)b*Tdim*Cdim + c;
    const float inv = 1.0f/(float)Kma;
    float w0t=tw[c*3+0], w1t=tw[c*3+1], w2t=tw[c*3+2], btc=tb[c];
    float w0s=sw[c*3+0], w1s=sw[c*3+1], w2s=sw[c*3+2], bsc=sb[c];

    int t0 = seg*SEGLEN, t1 = t0 + SEGLEN;
    float ws = 0.f;
    int tref = (seg==0) ? 0 : (t0-1);
    #pragma unroll 5
    for (int j = tref-(Kma-1); j <= tref; ++j) ws += xb[max(j,0)*Cdim];

    float tr_m1, tr_c, x_m1, x_c;
    if (seg == 0) {
        tr_c = ws*inv; tr_m1 = tr_c;
        x_c  = xb[0];  x_m1  = x_c;
    } else {
        tr_m1 = ws*inv;
        x_m1  = xb[(t0-1)*Cdim];
        ws   += xb[t0*Cdim] - xb[max(t0-Kma,0)*Cdim];
        tr_c  = ws*inv;
        x_c   = xb[t0*Cdim];
    }

    float Ssum = 0.f;
    #pragma unroll 4
    for (int t = t0; t < t1; ++t) {
        Ssum += tr_c;
        float tr_p, x_p;
        if (t+1 < Tdim) {
            x_p = xb[(t+1)*Cdim];
            ws += x_p - xb[max(t+1-Kma,0)*Cdim];
            tr_p = ws*inv;
        } else { x_p = x_c; tr_p = tr_c; }

        int o = (b*Tdim + t)*Cdim + c;
        float tctx = fmaf(tr_m1,w0t, fmaf(tr_c,w1t, fmaf(tr_p,w2t, btc)));
        g_xt[o] = tanhf(tctx);
        float sm1 = x_m1-tr_m1, sc = x_c-tr_c, spp = x_p-tr_p;
        g_sctx[o] = fmaf(sm1,w0s, fmaf(sc,w1s, fmaf(spp,w2s, bsc)));

        if (t == 0)      g_tr0[b*Cdim+c] = tr_c;
        if (t == Tdim-1) g_trN[b*Cdim+c] = tr_c;
        tr_m1 = tr_c; tr_c = tr_p; x_m1 = x_c; x_c = x_p;
    }
    g_Spart[seg][b*Cdim+c] = Ssum;
}

// ===================== K2: hypernetwork + psi ===============================
__global__ void hyper_kernel(const float* __restrict__ slw, const float* __restrict__ slb,
                             const float* __restrict__ w1,  const float* __restrict__ b1,
                             const float* __restrict__ w2,  const float* __restrict__ b2) {
    int b = blockIdx.x;
    int j = threadIdx.x;                 // 512 threads
    __shared__ float h[2*Cdim];
    __shared__ float h1[Cdim];
    __shared__ float params_s[2*NWv];
    __shared__ float da[NWv], db[NWv];

    {
        int c = j;
        float S = 0.f;
        #pragma unroll
        for (int s = 0; s < SEG; ++s) S += g_Spart[s][b*Cdim+c];
        float tr0 = g_tr0[b*Cdim+c], trN = g_trN[b*Cdim+c];
        float a0 = slw[c*3+0], a1 = slw[c*3+1], a2 = slw[c*3+2];
        float sp = (a0*(S + tr0 - trN) + a1*S + a2*(S - tr0 + trN)) * (1.0f/Tdim) + slb[c];
        h[c]        = sp;
        h[Cdim + c] = S * (1.0f/Tdim);
    }
    __syncthreads();

    {
        float a0=0.f, a1=0.f, a2=0.f, a3=0.f;
        #pragma unroll 4
        for (int i = 0; i < 2*Cdim; i += 4) {
            a0 = fmaf(h[i+0], w1[(i+0)*Cdim + j], a0);
            a1 = fmaf(h[i+1], w1[(i+1)*Cdim + j], a1);
            a2 = fmaf(h[i+2], w1[(i+2)*Cdim + j], a2);
            a3 = fmaf(h[i+3], w1[(i+3)*Cdim + j], a3);
        }
        float acc = ((a0+a1)+(a2+a3)) + b1[j];
        h1[j] = acc / (1.f + expf(-acc));
    }
    __syncthreads();

    {
        int warp = j >> 5, lane = j & 31;
        if (warp < 2*NWv) {
            float v = 0.f;
            for (int jj = lane; jj < Cdim; jj += 32) v = fmaf(h1[jj], w2[jj*(2*NWv) + warp], v);
            #pragma unroll
            for (int o = 16; o; o >>= 1) v += __shfl_down_sync(0xffffffffu, v, o);
            if (lane == 0) params_s[warp] = v + b2[warp];
        }
    }
    __syncthreads();
    if (j < NWv) {
        float a = params_s[j*2+0], bb = params_s[j*2+1];
        da[j] = ((a > 20.f) ? a : log1pf(expf(a))) + 0.01f;
        db[j] = (float)Tdim / (1.f + expf(-bb));
    }
    __syncthreads();

    for (int t = j; t < Tdim; t += blockDim.x) {
        #pragma unroll
        for (int w = 0; w < NWv; ++w) {
            float z  = ((float)t - db[w]) / da[w];
            float z2 = z*z;
            g_psi[(b*Tdim + t)*NWv + w] = (1.f - z2) * expf(-0.5f*z2);
        }
    }
}

// ===================== mma.sync GEMM ========================================
// C[16384,512] = A[16384,Ktot] @ W[Ktot,512], bf16 hi/lo split, 3 MMA terms.
// MODE 0: A = cheby basis of g_xt, C = g_tout (+bias0)
// MODE 1: A = psi (x) g_sctx,      C = g_sout
// MODE 2: A = g_tout,              C = g_amp (2*sigmoid)
#define GBM 128
#define GBN 128
#define GBK 32
#define SPAD 40                 // padded row stride (elems): 80B, conflict-free ldmatrix
// stage element offsets (bf16)
#define SO_AHI 0
#define SO_ALO (128*SPAD)
#define SO_BHI (2*128*SPAD)
#define SO_BLO (3*128*SPAD)
#define STAGE_ELEMS (4*128*SPAD)          // 20480 elems = 40960 B
#define SMEM_BYTES (2*STAGE_ELEMS*2)      // 81920 B

__device__ __forceinline__ void split2(float x, float y, uint32_t& h, uint32_t& l) {
    __nv_bfloat162 hv = __floats2bfloat162_rn(x, y);
    float hx = __bfloat162float(__low2bfloat16(hv));
    float hy = __bfloat162float(__high2bfloat16(hv));
    __nv_bfloat162 lv = __floats2bfloat162_rn(x - hx, y - hy);
    h = *reinterpret_cast<uint32_t*>(&hv);
    l = *reinterpret_cast<uint32_t*>(&lv);
}

__device__ __forceinline__ void ldmx4(uint32_t addr, uint32_t* r) {
    asm volatile("ldmatrix.sync.aligned.m8n8.x4.shared.b16 {%0,%1,%2,%3}, [%4];"
        : "=r"(r[0]), "=r"(r[1]), "=r"(r[2]), "=r"(r[3]) : "r"(addr));
}
__device__ __forceinline__ void mma16816(float* c, const uint32_t* a, const uint32_t* b) {
    asm volatile("mma.sync.aligned.m16n8k16.row.col.f32.bf16.bf16.f32 "
        "{%0,%1,%2,%3}, {%4,%5,%6,%7}, {%8,%9}, {%0,%1,%2,%3};"
        : "+f"(c[0]), "+f"(c[1]), "+f"(c[2]), "+f"(c[3])
        : "r"(a[0]), "r"(a[1]), "r"(a[2]), "r"(a[3]), "r"(b[0]), "r"(b[1]));
}
__device__ __forceinline__ uint32_t smem_u32(const void* p) {
    uint32_t a;
    asm("{ .reg .u64 t; cvta.to.shared.u64 t, %1; cvt.u32.u64 %0, t; }" : "=r"(a) : "l"(p));
    return a;
}

template<int MODE>
__global__ __launch_bounds__(256, 1)
void mma_gemm(const float* __restrict__ biasv) {
    extern __shared__ __nv_bfloat16 smem[];
    const float* Asrc = (MODE==0) ? g_xt : (MODE==1) ? g_sctx : g_tout;
    float*       Cout = (MODE==0) ? g_tout : (MODE==1) ? g_sout : g_amp;
    const __nv_bfloat16* Whi = (MODE==0) ? g_Wc_hi : (MODE==1) ? g_Ww_hi : g_Wa_hi;
    const __nv_bfloat16* Wlo = (MODE==0) ? g_Wc_lo : (MODE==1) ? g_Ww_lo : g_Wa_lo;
    const int Ktot = (MODE==0) ? 3*Cdim : (MODE==1) ? NWv*Cdim : Cdim;
    const int NKB  = Ktot / GBK;

    const int tid = threadIdx.x;
    const int lane = tid & 31, wid = tid >> 5;
    const int wm = wid >> 2, wn = wid & 3;      // warp grid 2(m) x 4(n)
    const int m0 = blockIdx.y * GBM, n0 = blockIdx.x * GBN;

    const int rA   = tid >> 1;          // 0..127 (A & B tile row)
    const int half = tid & 1;           // k half (16 elems)
    const float* aPtr = Asrc + (size_t)(m0 + rA)*Cdim + half*16;
    const __nv_bfloat16* bhPtr = Whi + (size_t)(n0 + rA)*Ktot + half*16;
    const __nv_bfloat16* blPtr = Wlo + (size_t)(n0 + rA)*Ktot + half*16;

    uint32_t sbase = smem_u32(smem);

    float   aPf[16];
    uint4   bPfH[2], bPfL[2];
    float   pScale = 1.f;
    float   acc[4][4][4];
    #pragma unroll
    for (int i = 0; i < 4; ++i)
        #pragma unroll
        for (int j = 0; j < 4; ++j)
            #pragma unroll
            for (int q = 0; q < 4; ++q) acc[i][j][q] = 0.f;

    // ---- global load for block kb into regs ----
    auto loadG = [&](int kb) {
        int sub = (MODE==2) ? 0 : (kb >> 4);
        int cb  = (MODE==2) ? kb*GBK : (kb & 15)*GBK;
        const float4* ap = reinterpret_cast<const float4*>(aPtr + cb);
        #pragma unroll
        for (int i = 0; i < 4; ++i) {
            float4 v = ap[i];
            aPf[i*4+0]=v.x; aPf[i*4+1]=v.y; aPf[i*4+2]=v.z; aPf[i*4+3]=v.w;
        }
        if (MODE == 1) pScale = g_psi[(m0 + rA)*NWv + sub];
        const uint4* bh = reinterpret_cast<const uint4*>(bhPtr + (size_t)kb*GBK);
        const uint4* bl = reinterpret_cast<const uint4*>(blPtr + (size_t)kb*GBK);
        bPfH[0] = bh[0]; bPfH[1] = bh[1];
        bPfL[0] = bl[0]; bPfL[1] = bl[1];
    };

    // ---- convert + store regs into smem stage ----
    auto storeS = [&](int buf, int kb) {
        int sub = (MODE==2) ? 0 : (kb >> 4);
        __nv_bfloat16* st = smem + buf*STAGE_ELEMS;
        uint32_t hv[8], lv[8];
        #pragma unroll
        for (int i = 0; i < 8; ++i) {
            float vx = aPf[i*2], vy = aPf[i*2+1];
            if (MODE == 0) {
                if (sub == 1) {
                    vx = fmaf(2.f*vx, vx, -1.f); vy = fmaf(2.f*vy, vy, -1.f);
                } else if (sub == 2) {
                    vx = vx*fmaf(4.f*vx, vx, -3.f); vy = vy*fmaf(4.f*vy, vy, -3.f);
                }
            } else if (MODE == 1) {
                vx *= pScale; vy *= pScale;
            }
            split2(vx, vy, hv[i], lv[i]);
        }
        uint32_t arow = (uint32_t)(rA*SPAD + half*16);
        #pragma unroll
        for (int i = 0; i < 2; ++i) {
            *reinterpret_cast<uint4*>(st + SO_AHI + arow + i*8) =
                make_uint4(hv[i*4+0], hv[i*4+1], hv[i*4+2], hv[i*4+3]);
            *reinterpret_cast<uint4*>(st + SO_ALO + arow + i*8) =
                make_uint4(lv[i*4+0], lv[i*4+1], lv[i*4+2], lv[i*4+3]);
        }
        *reinterpret_cast<uint4*>(st + SO_BHI + arow + 0) = bPfH[0];
        *reinterpret_cast<uint4*>(st + SO_BHI + arow + 8) = bPfH[1];
        *reinterpret_cast<uint4*>(st + SO_BLO + arow + 0) = bPfL[0];
        *reinterpret_cast<uint4*>(st + SO_BLO + arow + 8) = bPfL[1];
    };

    // ---- compute one stage (2 x k16 steps, 3 terms) ----
    const uint32_t aRowSel = (uint32_t)(lane & 15);
    const uint32_t aColSel = (uint32_t)(((lane >> 4) & 1) * 8);
    const uint32_t bRowSel = (uint32_t)(((lane >> 4) & 1) * 8 + (lane & 7));
    const uint32_t bColSel = (uint32_t)(((lane >> 3) & 1) * 8);
    auto compute = [&](int buf) {
        uint32_t sb = sbase + buf*STAGE_ELEMS*2;
        #pragma unroll
        for (int kk = 0; kk < 2; ++kk) {
            uint32_t kO = kk*16;
            uint32_t aH[4][4], aL[4][4], bH[4][2], bL[4][2];
            #pragma unroll
            for (int mt = 0; mt < 4; ++mt) {
                uint32_t row = wm*64 + mt*16 + aRowSel;
                uint32_t off = (row*SPAD + kO + aColSel)*2;
                ldmx4(sb + SO_AHI*2 + off, aH[mt]);
                ldmx4(sb + SO_ALO*2 + off, aL[mt]);
            }
            #pragma unroll
            for (int p = 0; p < 2; ++p) {
                uint32_t row = wn*32 + p*16 + bRowSel;
                uint32_t off = (row*SPAD + kO + bColSel)*2;
                uint32_t r4[4];
                ldmx4(sb + SO_BHI*2 + off, r4);
                bH[p*2+0][0]=r4[0]; bH[p*2+0][1]=r4[1];
                bH[p*2+1][0]=r4[2]; bH[p*2+1][1]=r4[3];
                ldmx4(sb + SO_BLO*2 + off, r4);
                bL[p*2+0][0]=r4[0]; bL[p*2+0][1]=r4[1];
                bL[p*2+1][0]=r4[2]; bL[p*2+1][1]=r4[3];
            }
            #pragma unroll
            for (int mt = 0; mt < 4; ++mt)
                #pragma unroll
                for (int nt = 0; nt < 4; ++nt) {
                    mma16816(acc[mt][nt], aH[mt], bH[nt]);
                    mma16816(acc[mt][nt], aH[mt], bL[nt]);
                    mma16816(acc[mt][nt], aL[mt], bH[nt]);
                }
        }
    };

    loadG(0);
    storeS(0, 0);
    __syncthreads();
    for (int kb = 0; kb < NKB; ++kb) {
        if (kb + 1 < NKB) loadG(kb + 1);
        compute(kb & 1);
        if (kb + 1 < NKB) storeS((kb + 1) & 1, kb + 1);
        __syncthreads();
    }

    // ---- epilogue: write C ----
    const int cRow = lane >> 2, cCol2 = (lane & 3)*2;
    #pragma unroll
    for (int mt = 0; mt < 4; ++mt) {
        #pragma unroll
        for (int nt = 0; nt < 4; ++nt) {
            int col = n0 + wn*32 + nt*8 + cCol2;
            float v0 = acc[mt][nt][0], v1 = acc[mt][nt][1];
            float v2 = acc[mt][nt][2], v3 = acc[mt][nt][3];
            if (MODE == 0) {
                float b0 = g_bias0[col], b1 = g_bias0[col+1];
                v0 += b0; v1 += b1; v2 += b0; v3 += b1;
            } else if (MODE == 2) {
                float b0 = biasv[col], b1 = biasv[col+1];
                v0 = 2.f/(1.f+expf(-(v0+b0))); v1 = 2.f/(1.f+expf(-(v1+b1)));
                v2 = 2.f/(1.f+expf(-(v2+b0))); v3 = 2.f/(1.f+expf(-(v3+b1)));
            }
            int row = m0 + wm*64 + mt*16 + cRow;
            *reinterpret_cast<float2*>(Cout + (size_t)row*Cdim + col)      = make_float2(v0, v1);
            *reinterpret_cast<float2*>(Cout + (size_t)(row+8)*Cdim + col)  = make_float2(v2, v3);
        }
    }
}

// ===================== K5: gate + residual + LayerNorm ======================
__global__ void epilogue_kernel(const float* __restrict__ x,
                                const float* __restrict__ gamma,
                                const float* __restrict__ beta,
                                float* __restrict__ out) {
    int m = blockIdx.x;
    int i = threadIdx.x;            // 128 threads, 4 floats each
    size_t bse = (size_t)m*Cdim + i*4;
    float4 to = *reinterpret_cast<const float4*>(&g_tout[bse]);
    float4 sp = *reinterpret_cast<const float4*>(&g_sout[bse]);
    float4 am = *reinterpret_cast<const float4*>(&g_amp[bse]);
    float4 xv = *reinterpret_cast<const float4*>(&x[bse]);
    float4 y;
    y.x = fmaf(sp.x, am.x, to.x) + xv.x;
    y.y = fmaf(sp.y, am.y, to.y) + xv.y;
    y.z = fmaf(sp.z, am.z, to.z) + xv.z;
    y.w = fmaf(sp.w, am.w, to.w) + xv.w;

    float s  = y.x + y.y + y.z + y.w;
    float sq = y.x*y.x + y.y*y.y + y.z*y.z + y.w*y.w;
    #pragma unroll
    for (int o = 16; o; o >>= 1) {
        s  += __shfl_down_sync(0xffffffffu, s,  o);
        sq += __shfl_down_sync(0xffffffffu, sq, o);
    }
    __shared__ float rs[4], rq[4];
    int warp = i >> 5, lane = i & 31;
    if (lane == 0) { rs[warp] = s; rq[warp] = sq; }
    __syncthreads();
    float ts = rs[0]+rs[1]+rs[2]+rs[3];
    float tq = rq[0]+rq[1]+rq[2]+rq[3];
    float mu  = ts * (1.0f/Cdim);
    float var = tq * (1.0f/Cdim) - mu*mu;
    float r = rsqrtf(var + 1e-5f);

    float4 g = *reinterpret_cast<const float4*>(&gamma[i*4]);
    float4 bb= *reinterpret_cast<const float4*>(&beta[i*4]);
    float4 o4;
    o4.x = (y.x-mu)*r*g.x + bb.x;
    o4.y = (y.y-mu)*r*g.y + bb.y;
    o4.z = (y.z-mu)*r*g.z + bb.z;
    o4.w = (y.w-mu)*r*g.w + bb.w;
    *reinterpret_cast<float4*>(&out[bse]) = o4;
}

// ===================== launch ===============================================
extern "C" void kernel_launch(void* const* d_in, const int* in_sizes, int n_in,
                              void* d_out, int out_size) {
    const float* x     = (const float*)d_in[0];
    const float* tw    = (const float*)d_in[1];
    const float* tb    = (const float*)d_in[2];
    const float* sw    = (const float*)d_in[3];
    const float* sb    = (const float*)d_in[4];
    const float* slw   = (const float*)d_in[5];
    const float* slb   = (const float*)d_in[6];
    const float* cheby = (const float*)d_in[7];
    const float* hw1   = (const float*)d_in[8];
    const float* hb1   = (const float*)d_in[9];
    const float* hw2   = (const float*)d_in[10];
    const float* hb2   = (const float*)d_in[11];
    const float* amp_w = (const float*)d_in[12];
    const float* amp_b = (const float*)d_in[13];
    const float* wav_w = (const float*)d_in[14];
    const float* gamma = (const float*)d_in[15];
    const float* beta  = (const float*)d_in[16];
    float* out = (float*)d_out;

    cudaFuncSetAttribute(mma_gemm<0>, cudaFuncAttributeMaxDynamicSharedMemorySize, SMEM_BYTES);
    cudaFuncSetAttribute(mma_gemm<1>, cudaFuncAttributeMaxDynamicSharedMemorySize, SMEM_BYTES);
    cudaFuncSetAttribute(mma_gemm<2>, cudaFuncAttributeMaxDynamicSharedMemorySize, SMEM_BYTES);

    bias0_kernel<<<1, 512>>>(cheby);
    {
        dim3 blk(32, 8);
        prepW_kernel<0><<<dim3(3*Cdim/32, Cdim/32), blk>>>(cheby);
        prepW_kernel<1><<<dim3(NWv*Cdim/32, Cdim/32), blk>>>(wav_w);
        prepW_kernel<2><<<dim3(Cdim/32, Cdim/32), blk>>>(amp_w);
    }
    decomp_kernel<<<(SEG*Bdim*Cdim)/256, 256>>>(x, tw, tb, sw, sb);
    hyper_kernel<<<Bdim, 512>>>(slw, slb, hw1, hb1, hw2, hb2);

    dim3 grid(Cdim/GBN, Mrows/GBM);   // (4, 128)
    mma_gemm<0><<<grid, 256, SMEM_BYTES>>>(nullptr);  // cheby   K=1536
    mma_gemm<1><<<grid, 256, SMEM_BYTES>>>(nullptr);  // wavelet K=2048
    mma_gemm<2><<<grid, 256, SMEM_BYTES>>>(amp_b);    // amp     K=512

    epilogue_kernel<<<Mrows, 128>>>(x, gamma, beta, out);
}

// round 4
// speedup vs baseline: 3.3258x; 1.8021x over previous
#include <cuda_runtime.h>
#include <cuda_fp16.h>
#include <cstdint>
#include <math.h>

#define Bdim 16
#define Tdim 1024
#define Cdim 512
#define Kma  25
#define NWv  4
#define Mrows (Bdim*Tdim)   // 16384
#define SEG  8
#define SEGLEN (Tdim/SEG)   // 128

// ===================== scratch ==============================================
__device__ __half g_Ac16[Mrows*3*Cdim];   // cheby basis A, [m][k=(d-1)*512+c]
__device__ __half g_sA16[Mrows*Cdim];     // spike_ctx fp16 (wavelet A base)
__device__ __half g_Aa16[Mrows*Cdim];     // tout fp16 (amp A)
__device__ float  g_tout[Mrows*Cdim];
__device__ float  g_sout[Mrows*Cdim];
__device__ float  g_amp [Mrows*Cdim];
__device__ float  g_bias0[Cdim];
__device__ float  g_Spart[SEG][Bdim*Cdim];
__device__ float  g_tr0[Bdim*Cdim];
__device__ float  g_trN[Bdim*Cdim];
__device__ float  g_h  [Bdim*2*Cdim];
__device__ float  g_h1 [Bdim*Cdim];
__device__ float  g_wp [Bdim*2*NWv];      // [b][w*2 + {0:da,1:db}]
// weights transposed to [o][k], fp16
__device__ __half g_Wc16[Cdim*3*Cdim];
__device__ __half g_Ww16[Cdim*NWv*Cdim];
__device__ __half g_Wa16[Cdim*Cdim];

// ===================== helpers ==============================================
__device__ __forceinline__ uint32_t smem_u32(const void* p) {
    uint32_t a;
    asm("{ .reg .u64 t; cvta.to.shared.u64 t, %1; cvt.u32.u64 %0, t; }" : "=r"(a) : "l"(p));
    return a;
}
__device__ __forceinline__ void cp16(uint32_t dst, const void* src) {
    asm volatile("cp.async.cg.shared.global [%0], [%1], 16;" :: "r"(dst), "l"(src));
}
__device__ __forceinline__ void cp_commit() { asm volatile("cp.async.commit_group;"); }
template<int N> __device__ __forceinline__ void cp_wait() {
    asm volatile("cp.async.wait_group %0;" :: "n"(N));
}
__device__ __forceinline__ void ldmx4(uint32_t addr, uint32_t* r) {
    asm volatile("ldmatrix.sync.aligned.m8n8.x4.shared.b16 {%0,%1,%2,%3}, [%4];"
        : "=r"(r[0]), "=r"(r[1]), "=r"(r[2]), "=r"(r[3]) : "r"(addr));
}
__device__ __forceinline__ void mma16816(float* c, const uint32_t* a, const uint32_t* b) {
    asm volatile("mma.sync.aligned.m16n8k16.row.col.f32.f16.f16.f32 "
        "{%0,%1,%2,%3}, {%4,%5,%6,%7}, {%8,%9}, {%0,%1,%2,%3};"
        : "+f"(c[0]), "+f"(c[1]), "+f"(c[2]), "+f"(c[3])
        : "r"(a[0]), "r"(a[1]), "r"(a[2]), "r"(a[3]), "r"(b[0]), "r"(b[1]));
}
__device__ __forceinline__ uint32_t hmul2u(uint32_t a, uint32_t b) {
    __half2 r = __hmul2(*reinterpret_cast<__half2*>(&a), *reinterpret_cast<__half2*>(&b));
    return *reinterpret_cast<uint32_t*>(&r);
}

// ===================== K0a: bias0 ===========================================
__global__ void bias0_kernel(const float* __restrict__ cheby) {
    int o = threadIdx.x;
    float s = 0.f;
    for (int c = 0; c < Cdim; ++c) s += cheby[(c*Cdim + o)*4];
    g_bias0[o] = s;
}

// ===================== K0b: weight transpose -> fp16 ========================
template<int MODE>
__global__ void prepW_kernel(const float* __restrict__ src) {
    __half* dst = (MODE==0) ? g_Wc16 : (MODE==1) ? g_Ww16 : g_Wa16;
    const int Ktot = (MODE==0) ? 3*Cdim : (MODE==1) ? NWv*Cdim : Cdim;
    __shared__ float tile[32][33];
    int kb = blockIdx.x*32, ob = blockIdx.y*32;
    int tx = threadIdx.x, ty = threadIdx.y;   // 32 x 8
    #pragma unroll
    for (int s = 0; s < 32; s += 8) {
        int k = kb + ty + s, o = ob + tx;
        float v;
        if (MODE == 0) { int d = k >> 9, c = k & 511; v = src[(c*Cdim + o)*4 + d + 1]; }
        else           { v = src[(size_t)k*Cdim + o]; }
        tile[ty+s][tx] = v;
    }
    __syncthreads();
    #pragma unroll
    for (int s = 0; s < 32; s += 8) {
        int o = ob + ty + s, k = kb + tx;
        dst[(size_t)o*Ktot + k] = __float2half_rn(tile[tx][ty+s]);
    }
}

// ===================== K1: fused decomposition ==============================
// per (seg,b,c): causal MA(25), spike split, dwconv3 both paths, cheby basis
// -> g_Ac16 fp16, spike ctx -> g_sA16 fp16, pooling stats.
__global__ void decomp_kernel(const float* __restrict__ x,
                              const float* __restrict__ tw, const float* __restrict__ tb,
                              const float* __restrict__ sw, const float* __restrict__ sb) {
    int idx = blockIdx.x*blockDim.x + threadIdx.x;
    int c   = idx & (Cdim-1);
    int tmp = idx >> 9;
    int b   = tmp & (Bdim-1);
    int seg = tmp >> 4;
    const float* xb = x + (size_t)b*Tdim*Cdim + c;
    const float inv = 1.0f/(float)Kma;
    float w0t=tw[c*3+0], w1t=tw[c*3+1], w2t=tw[c*3+2], btc=tb[c];
    float w0s=sw[c*3+0], w1s=sw[c*3+1], w2s=sw[c*3+2], bsc=sb[c];

    int t0 = seg*SEGLEN, t1 = t0 + SEGLEN;
    float ws = 0.f;
    int tref = (seg==0) ? 0 : (t0-1);
    #pragma unroll 5
    for (int j = tref-(Kma-1); j <= tref; ++j) ws += xb[max(j,0)*Cdim];

    float tr_m1, tr_c, x_m1, x_c;
    if (seg == 0) {
        tr_c = ws*inv; tr_m1 = tr_c;
        x_c  = xb[0];  x_m1  = x_c;
    } else {
        tr_m1 = ws*inv;
        x_m1  = xb[(t0-1)*Cdim];
        ws   += xb[t0*Cdim] - xb[max(t0-Kma,0)*Cdim];
        tr_c  = ws*inv;
        x_c   = xb[t0*Cdim];
    }

    float Ssum = 0.f;
    #pragma unroll 4
    for (int t = t0; t < t1; ++t) {
        Ssum += tr_c;
        float tr_p, x_p;
        if (t+1 < Tdim) {
            x_p = xb[(t+1)*Cdim];
            ws += x_p - xb[max(t+1-Kma,0)*Cdim];
            tr_p = ws*inv;
        } else { x_p = x_c; tr_p = tr_c; }

        int m = b*Tdim + t;
        float tctx = fmaf(tr_m1,w0t, fmaf(tr_c,w1t, fmaf(tr_p,w2t, btc)));
        float xt = tanhf(tctx);
        float d2 = fmaf(2.f*xt, xt, -1.f);
        float d3 = xt * fmaf(4.f*xt, xt, -3.f);
        size_t arow = (size_t)m*(3*Cdim) + c;
        g_Ac16[arow]          = __float2half_rn(xt);
        g_Ac16[arow + Cdim]   = __float2half_rn(d2);
        g_Ac16[arow + 2*Cdim] = __float2half_rn(d3);

        float sm1 = x_m1-tr_m1, sc = x_c-tr_c, spp = x_p-tr_p;
        float sctx = fmaf(sm1,w0s, fmaf(sc,w1s, fmaf(spp,w2s, bsc)));
        g_sA16[(size_t)m*Cdim + c] = __float2half_rn(sctx);

        if (t == 0)      g_tr0[b*Cdim+c] = tr_c;
        if (t == Tdim-1) g_trN[b*Cdim+c] = tr_c;
        tr_m1 = tr_c; tr_c = tr_p; x_m1 = x_c; x_c = x_p;
    }
    g_Spart[seg][b*Cdim+c] = Ssum;
}

// ===================== K2: hypernetwork (3 stages) ==========================
__global__ void hyper_pool(const float* __restrict__ slw, const float* __restrict__ slb) {
    int b = blockIdx.x, c = threadIdx.x;   // 16 x 512
    float S = 0.f;
    #pragma unroll
    for (int s = 0; s < SEG; ++s) S += g_Spart[s][b*Cdim+c];
    float tr0 = g_tr0[b*Cdim+c], trN = g_trN[b*Cdim+c];
    float a0 = slw[c*3+0], a1 = slw[c*3+1], a2 = slw[c*3+2];
    float sp = (a0*(S + tr0 - trN) + a1*S + a2*(S - tr0 + trN)) * (1.0f/Tdim) + slb[c];
    g_h[b*2*Cdim + c]        = sp;
    g_h[b*2*Cdim + Cdim + c] = S * (1.0f/Tdim);
}

__global__ void hyper_mm(const float* __restrict__ w1, const float* __restrict__ b1) {
    int b = blockIdx.y;
    int col = blockIdx.x*128 + threadIdx.x;   // grid (4,16) x 128
    __shared__ float hs[2*Cdim];
    for (int i = threadIdx.x; i < 2*Cdim; i += 128) hs[i] = g_h[b*2*Cdim + i];
    __syncthreads();
    float a0=0.f, a1=0.f, a2=0.f, a3=0.f;
    #pragma unroll 4
    for (int i = 0; i < 2*Cdim; i += 4) {
        a0 = fmaf(hs[i+0], w1[(i+0)*Cdim + col], a0);
        a1 = fmaf(hs[i+1], w1[(i+1)*Cdim + col], a1);
        a2 = fmaf(hs[i+2], w1[(i+2)*Cdim + col], a2);
        a3 = fmaf(hs[i+3], w1[(i+3)*Cdim + col], a3);
    }
    float acc = ((a0+a1)+(a2+a3)) + b1[col];
    g_h1[b*Cdim + col] = acc / (1.f + expf(-acc));
}

__global__ void hyper_psi(const float* __restrict__ w2, const float* __restrict__ b2) {
    int b = blockIdx.x;
    int j = threadIdx.x;                      // 256
    int warp = j >> 5, lane = j & 31;
    __shared__ float params_s[2*NWv];
    if (warp < 2*NWv) {
        float v = 0.f;
        for (int jj = lane; jj < Cdim; jj += 32)
            v = fmaf(g_h1[b*Cdim + jj], w2[jj*(2*NWv) + warp], v);
        #pragma unroll
        for (int o = 16; o; o >>= 1) v += __shfl_down_sync(0xffffffffu, v, o);
        if (lane == 0) params_s[warp] = v + b2[warp];
    }
    __syncthreads();
    if (j < NWv) {
        float a = params_s[j*2+0], bb = params_s[j*2+1];
        g_wp[b*2*NWv + j*2 + 0] = ((a > 20.f) ? a : log1pf(expf(a))) + 0.01f;
        g_wp[b*2*NWv + j*2 + 1] = (float)Tdim / (1.f + expf(-bb));
    }
}

// ===================== fp16 mma GEMM (cp.async, 4 stages) ===================
// mode 0: tout = Acheby @ Wc + bias0 ; also writes tout fp16 -> g_Aa16
// mode 1: sout = (psi ⊗ sctx) @ Ww   ; psi applied to A fragments
// mode 2: amp  = 2*sigmoid(tout16 @ Wa + amp_b)
#define SPADH 40
#define TO_B  (128*SPADH*2)            // 10240 B
#define STG_BYTES (2*128*SPADH*2)      // 20480 B
#define NSTAGE 4
#define SMEM_GEMM (NSTAGE*STG_BYTES)   // 81920 B

__global__ __launch_bounds__(256, 1)
void gemm_kernel(int modeBase, const float* __restrict__ ampb) {
    int mode = modeBase + (int)blockIdx.z;
    const __half *Ag, *Bg; float* Cout; int Ktot;
    if (mode == 0)      { Ag = g_Ac16; Bg = g_Wc16; Cout = g_tout; Ktot = 3*Cdim; }
    else if (mode == 1) { Ag = g_sA16; Bg = g_Ww16; Cout = g_sout; Ktot = NWv*Cdim; }
    else                { Ag = g_Aa16; Bg = g_Wa16; Cout = g_amp;  Ktot = Cdim; }
    const int NKB = Ktot / 32;
    const int AK  = (mode == 1) ? Cdim : Ktot;   // A row length (wavelet wraps)

    extern __shared__ char smem[];
    uint32_t sbase = smem_u32(smem);
    int tid = threadIdx.x, lane = tid & 31, wid = tid >> 5;
    int wm = wid >> 2, wn = wid & 3;
    int m0 = blockIdx.y * 128, n0 = blockIdx.x * 128;

    int r = tid >> 1, hf_ = tid & 1;
    const __half* gA = Ag + (size_t)(m0 + r)*AK + hf_*16;
    const __half* gB = Bg + (size_t)(n0 + r)*Ktot + hf_*16;
    uint32_t sAd = sbase + (uint32_t)(r*SPADH + hf_*16)*2;
    uint32_t sBd = sAd + TO_B;

    auto issue = [&](int kb) {
        uint32_t so = (uint32_t)(kb & (NSTAGE-1))*STG_BYTES;
        int ak = (mode == 1) ? (kb & 15)*32 : kb*32;
        const __half* pa = gA + ak;
        const __half* pb = gB + (size_t)kb*32;
        cp16(sAd + so, pa); cp16(sAd + so + 16, pa + 8);
        cp16(sBd + so, pb); cp16(sBd + so + 16, pb + 8);
    };

    float acc[4][4][4];
    #pragma unroll
    for (int i = 0; i < 4; ++i)
        #pragma unroll
        for (int j = 0; j < 4; ++j)
            #pragma unroll
            for (int q = 0; q < 4; ++q) acc[i][j][q] = 0.f;

    uint32_t ph1[4], ph2[4];
    const int bIdx = m0 >> 10;
    const int tbase = m0 & (Tdim-1);

    const uint32_t aRowSel = lane & 15;
    const uint32_t aColSel = ((lane >> 4) & 1)*8;
    const uint32_t bRowSel = ((lane >> 4) & 1)*8 + (lane & 7);
    const uint32_t bColSel = ((lane >> 3) & 1)*8;

    const int NP = (NSTAGE-1 < NKB) ? NSTAGE-1 : NKB;
    for (int s = 0; s < NP; ++s) { issue(s); cp_commit(); }

    for (int kb = 0; kb < NKB; ++kb) {
        if (mode == 1 && (kb & 15) == 0) {
            int w = kb >> 4;
            float da = g_wp[bIdx*8 + w*2], dbv = g_wp[bIdx*8 + w*2 + 1];
            #pragma unroll
            for (int mt = 0; mt < 4; ++mt) {
                float t1 = (float)(tbase + wm*64 + mt*16 + (int)(lane >> 2));
                float z = (t1 - dbv)/da, z2 = z*z;
                float p1 = (1.f - z2)*expf(-0.5f*z2);
                float t2 = t1 + 8.f;
                z = (t2 - dbv)/da; z2 = z*z;
                float p2 = (1.f - z2)*expf(-0.5f*z2);
                __half2 h1v = __half2half2(__float2half_rn(p1));
                __half2 h2v = __half2half2(__float2half_rn(p2));
                ph1[mt] = *reinterpret_cast<uint32_t*>(&h1v);
                ph2[mt] = *reinterpret_cast<uint32_t*>(&h2v);
            }
        }
        cp_wait<NSTAGE-2>();
        __syncthreads();

        uint32_t sb = sbase + (uint32_t)(kb & (NSTAGE-1))*STG_BYTES;
        #pragma unroll
        for (int kk = 0; kk < 2; ++kk) {
            uint32_t kO = kk*16;
            uint32_t aF[4][4], bF[4][2];
            #pragma unroll
            for (int mt = 0; mt < 4; ++mt) {
                uint32_t row = wm*64 + mt*16 + aRowSel;
                ldmx4(sb + (row*SPADH + kO + aColSel)*2, aF[mt]);
            }
            if (mode == 1) {
                #pragma unroll
                for (int mt = 0; mt < 4; ++mt) {
                    aF[mt][0] = hmul2u(aF[mt][0], ph1[mt]);
                    aF[mt][2] = hmul2u(aF[mt][2], ph1[mt]);
                    aF[mt][1] = hmul2u(aF[mt][1], ph2[mt]);
                    aF[mt][3] = hmul2u(aF[mt][3], ph2[mt]);
                }
            }
            #pragma unroll
            for (int p = 0; p < 2; ++p) {
                uint32_t row = wn*32 + p*16 + bRowSel;
                uint32_t r4[4];
                ldmx4(sb + TO_B + (row*SPADH + kO + bColSel)*2, r4);
                bF[p*2+0][0] = r4[0]; bF[p*2+0][1] = r4[1];
                bF[p*2+1][0] = r4[2]; bF[p*2+1][1] = r4[3];
            }
            #pragma unroll
            for (int mt = 0; mt < 4; ++mt)
                #pragma unroll
                for (int nt = 0; nt < 4; ++nt)
                    mma16816(acc[mt][nt], aF[mt], bF[nt]);
        }
        if (kb + NSTAGE-1 < NKB) issue(kb + NSTAGE-1);
        cp_commit();
    }

    // ---- epilogue ----
    const int cRow = lane >> 2, cCol2 = (lane & 3)*2;
    #pragma unroll
    for (int mt = 0; mt < 4; ++mt) {
        #pragma unroll
        for (int nt = 0; nt < 4; ++nt) {
            int col = n0 + wn*32 + nt*8 + cCol2;
            float v0 = acc[mt][nt][0], v1 = acc[mt][nt][1];
            float v2 = acc[mt][nt][2], v3 = acc[mt][nt][3];
            int row = m0 + wm*64 + mt*16 + cRow;
            if (mode == 0) {
                float b0 = g_bias0[col], b1 = g_bias0[col+1];
                v0 += b0; v1 += b1; v2 += b0; v3 += b1;
                *reinterpret_cast<__half2*>(&g_Aa16[(size_t)row*Cdim + col]) =
                    __floats2half2_rn(v0, v1);
                *reinterpret_cast<__half2*>(&g_Aa16[(size_t)(row+8)*Cdim + col]) =
                    __floats2half2_rn(v2, v3);
            } else if (mode == 2) {
                float b0 = ampb[col], b1 = ampb[col+1];
                v0 = 2.f/(1.f+expf(-(v0+b0))); v1 = 2.f/(1.f+expf(-(v1+b1)));
                v2 = 2.f/(1.f+expf(-(v2+b0))); v3 = 2.f/(1.f+expf(-(v3+b1)));
            }
            *reinterpret_cast<float2*>(Cout + (size_t)row*Cdim + col)     = make_float2(v0, v1);
            *reinterpret_cast<float2*>(Cout + (size_t)(row+8)*Cdim + col) = make_float2(v2, v3);
        }
    }
}

// ===================== K5: gate + residual + LayerNorm ======================
__global__ void epilogue_kernel(const float* __restrict__ x,
                                const float* __restrict__ gamma,
                                const float* __restrict__ beta,
                                float* __restrict__ out) {
    int m = blockIdx.x;
    int i = threadIdx.x;            // 128 threads, 4 floats each
    size_t bse = (size_t)m*Cdim + i*4;
    float4 to = *reinterpret_cast<const float4*>(&g_tout[bse]);
    float4 sp = *reinterpret_cast<const float4*>(&g_sout[bse]);
    float4 am = *reinterpret_cast<const float4*>(&g_amp[bse]);
    float4 xv = *reinterpret_cast<const float4*>(&x[bse]);
    float4 y;
    y.x = fmaf(sp.x, am.x, to.x) + xv.x;
    y.y = fmaf(sp.y, am.y, to.y) + xv.y;
    y.z = fmaf(sp.z, am.z, to.z) + xv.z;
    y.w = fmaf(sp.w, am.w, to.w) + xv.w;

    float s  = y.x + y.y + y.z + y.w;
    float sq = y.x*y.x + y.y*y.y + y.z*y.z + y.w*y.w;
    #pragma unroll
    for (int o = 16; o; o >>= 1) {
        s  += __shfl_down_sync(0xffffffffu, s,  o);
        sq += __shfl_down_sync(0xffffffffu, sq, o);
    }
    __shared__ float rs[4], rq[4];
    int warp = i >> 5, lane = i & 31;
    if (lane == 0) { rs[warp] = s; rq[warp] = sq; }
    __syncthreads();
    float ts = rs[0]+rs[1]+rs[2]+rs[3];
    float tq = rq[0]+rq[1]+rq[2]+rq[3];
    float mu  = ts * (1.0f/Cdim);
    float var = tq * (1.0f/Cdim) - mu*mu;
    float r = rsqrtf(var + 1e-5f);

    float4 g = *reinterpret_cast<const float4*>(&gamma[i*4]);
    float4 bb= *reinterpret_cast<const float4*>(&beta[i*4]);
    float4 o4;
    o4.x = (y.x-mu)*r*g.x + bb.x;
    o4.y = (y.y-mu)*r*g.y + bb.y;
    o4.z = (y.z-mu)*r*g.z + bb.z;
    o4.w = (y.w-mu)*r*g.w + bb.w;
    *reinterpret_cast<float4*>(&out[bse]) = o4;
}

// ===================== launch ===============================================
extern "C" void kernel_launch(void* const* d_in, const int* in_sizes, int n_in,
                              void* d_out, int out_size) {
    const float* x     = (const float*)d_in[0];
    const float* tw    = (const float*)d_in[1];
    const float* tb    = (const float*)d_in[2];
    const float* sw    = (const float*)d_in[3];
    const float* sb    = (const float*)d_in[4];
    const float* slw   = (const float*)d_in[5];
    const float* slb   = (const float*)d_in[6];
    const float* cheby = (const float*)d_in[7];
    const float* hw1   = (const float*)d_in[8];
    const float* hb1   = (const float*)d_in[9];
    const float* hw2   = (const float*)d_in[10];
    const float* hb2   = (const float*)d_in[11];
    const float* amp_w = (const float*)d_in[12];
    const float* amp_b = (const float*)d_in[13];
    const float* wav_w = (const float*)d_in[14];
    const float* gamma = (const float*)d_in[15];
    const float* beta  = (const float*)d_in[16];
    float* out = (float*)d_out;

    cudaFuncSetAttribute(gemm_kernel, cudaFuncAttributeMaxDynamicSharedMemorySize, SMEM_GEMM);

    bias0_kernel<<<1, 512>>>(cheby);
    {
        dim3 blk(32, 8);
        prepW_kernel<0><<<dim3(3*Cdim/32, Cdim/32), blk>>>(cheby);
        prepW_kernel<1><<<dim3(NWv*Cdim/32, Cdim/32), blk>>>(wav_w);
        prepW_kernel<2><<<dim3(Cdim/32, Cdim/32), blk>>>(amp_w);
    }
    decomp_kernel<<<(SEG*Bdim*Cdim)/256, 256>>>(x, tw, tb, sw, sb);
    hyper_pool<<<Bdim, 512>>>(slw, slb);
    hyper_mm<<<dim3(4, Bdim), 128>>>(hw1, hb1);
    hyper_psi<<<Bdim, 256>>>(hw2, hb2);

    gemm_kernel<<<dim3(4, Mrows/128, 2), 256, SMEM_GEMM>>>(0, nullptr);  // cheby + wavelet
    gemm_kernel<<<dim3(4, Mrows/128, 1), 256, SMEM_GEMM>>>(2, amp_b);    // amp gate

    epilogue_kernel<<<Mrows, 128>>>(x, gamma, beta, out);
}

// round 5
// speedup vs baseline: 3.8244x; 1.1499x over previous
#include <cuda_runtime.h>
#include <cuda_fp16.h>
#include <cstdint>
#include <math.h>

#define Bdim 16
#define Tdim 1024
#define Cdim 512
#define Kma  25
#define NWv  4
#define Mrows (Bdim*Tdim)   // 16384
#define SEG  8
#define SEGLEN (Tdim/SEG)   // 128

// ===================== scratch ==============================================
__device__ __half g_Ac16[Mrows*3*Cdim];   // cheby basis A, [m][k=(d-1)*512+c]
__device__ __half g_sA16[Mrows*Cdim];     // spike_ctx fp16 (wavelet A base)
__device__ __half g_Aa16[Mrows*Cdim];     // tout fp16 (amp A)
__device__ float  g_tout[Mrows*Cdim];     // trend_out fp32
__device__ __half g_s16 [Mrows*Cdim];     // spike_out fp16
__device__ __half g_a16 [Mrows*Cdim];     // amp_scale fp16
__device__ float  g_bias0[Cdim];
__device__ float  g_Spart[SEG][Bdim*Cdim];
__device__ float  g_tr0[Bdim*Cdim];
__device__ float  g_trN[Bdim*Cdim];
__device__ float  g_h  [Bdim*2*Cdim];
__device__ float  g_h1 [Bdim*Cdim];
__device__ float  g_wp [Bdim*2*NWv];      // [b][w*2 + {0:da,1:db}]
// weights transposed to [o][k], fp16
__device__ __half g_Wc16[Cdim*3*Cdim];
__device__ __half g_Ww16[Cdim*NWv*Cdim];
__device__ __half g_Wa16[Cdim*Cdim];

// ===================== helpers ==============================================
__device__ __forceinline__ uint32_t smem_u32(const void* p) {
    uint32_t a;
    asm("{ .reg .u64 t; cvta.to.shared.u64 t, %1; cvt.u32.u64 %0, t; }" : "=r"(a) : "l"(p));
    return a;
}
__device__ __forceinline__ void cp16(uint32_t dst, const void* src) {
    asm volatile("cp.async.cg.shared.global [%0], [%1], 16;" :: "r"(dst), "l"(src));
}
__device__ __forceinline__ void cp_commit() { asm volatile("cp.async.commit_group;"); }
template<int N> __device__ __forceinline__ void cp_wait() {
    asm volatile("cp.async.wait_group %0;" :: "n"(N));
}
__device__ __forceinline__ void ldmx4(uint32_t addr, uint32_t* r) {
    asm volatile("ldmatrix.sync.aligned.m8n8.x4.shared.b16 {%0,%1,%2,%3}, [%4];"
        : "=r"(r[0]), "=r"(r[1]), "=r"(r[2]), "=r"(r[3]) : "r"(addr));
}
__device__ __forceinline__ void mma16816(float* c, const uint32_t* a, const uint32_t* b) {
    asm volatile("mma.sync.aligned.m16n8k16.row.col.f32.f16.f16.f32 "
        "{%0,%1,%2,%3}, {%4,%5,%6,%7}, {%8,%9}, {%0,%1,%2,%3};"
        : "+f"(c[0]), "+f"(c[1]), "+f"(c[2]), "+f"(c[3])
        : "r"(a[0]), "r"(a[1]), "r"(a[2]), "r"(a[3]), "r"(b[0]), "r"(b[1]));
}
__device__ __forceinline__ uint32_t hmul2u(uint32_t a, uint32_t b) {
    __half2 r = __hmul2(*reinterpret_cast<__half2*>(&a), *reinterpret_cast<__half2*>(&b));
    return *reinterpret_cast<uint32_t*>(&r);
}

// ===================== K0: fused weight prep (all 4 jobs) ===================
// blocks [0,768)    : cheby transpose  (48 x 16 tiles)
// blocks [768,1792) : wavelet transpose (64 x 16 tiles)
// blocks [1792,2048): amp transpose    (16 x 16 tiles)
// block  2048       : bias0
__global__ void prep_all(const float* __restrict__ cheby,
                         const float* __restrict__ wav_w,
                         const float* __restrict__ amp_w) {
    int bx = blockIdx.x;
    int tx = threadIdx.x & 31, ty = threadIdx.x >> 5;   // 32 x 8

    if (bx == 2048) {
        for (int o = threadIdx.x; o < Cdim; o += 256) {
            float s = 0.f;
            for (int c = 0; c < Cdim; ++c) s += cheby[(c*Cdim + o)*4];
            g_bias0[o] = s;
        }
        return;
    }

    const float* src; __half* dst; int Ktot, kb, ob, mode;
    if (bx < 768)       { mode = 0; src = cheby; dst = g_Wc16; Ktot = 3*Cdim;
                          kb = (bx % 48)*32;  ob = (bx / 48)*32; }
    else if (bx < 1792) { mode = 1; src = wav_w; dst = g_Ww16; Ktot = NWv*Cdim;
                          int i = bx - 768;  kb = (i % 64)*32; ob = (i / 64)*32; }
    else                { mode = 2; src = amp_w; dst = g_Wa16; Ktot = Cdim;
                          int i = bx - 1792; kb = (i % 16)*32; ob = (i / 16)*32; }

    __shared__ float tile[32][33];
    #pragma unroll
    for (int s = 0; s < 32; s += 8) {
        int k = kb + ty + s, o = ob + tx;
        float v;
        if (mode == 0) { int d = k >> 9, c = k & 511; v = src[(c*Cdim + o)*4 + d + 1]; }
        else           { v = src[(size_t)k*Cdim + o]; }
        tile[ty+s][tx] = v;
    }
    __syncthreads();
    #pragma unroll
    for (int s = 0; s < 32; s += 8) {
        int o = ob + ty + s, k = kb + tx;
        dst[(size_t)o*Ktot + k] = __float2half_rn(tile[tx][ty+s]);
    }
}

// ===================== K1: fused decomposition ==============================
__global__ void decomp_kernel(const float* __restrict__ x,
                              const float* __restrict__ tw, const float* __restrict__ tb,
                              const float* __restrict__ sw, const float* __restrict__ sb) {
    int idx = blockIdx.x*blockDim.x + threadIdx.x;
    int c   = idx & (Cdim-1);
    int tmp = idx >> 9;
    int b   = tmp & (Bdim-1);
    int seg = tmp >> 4;
    const float* xb = x + (size_t)b*Tdim*Cdim + c;
    const float inv = 1.0f/(float)Kma;
    float w0t=tw[c*3+0], w1t=tw[c*3+1], w2t=tw[c*3+2], btc=tb[c];
    float w0s=sw[c*3+0], w1s=sw[c*3+1], w2s=sw[c*3+2], bsc=sb[c];

    int t0 = seg*SEGLEN, t1 = t0 + SEGLEN;
    float ws = 0.f;
    int tref = (seg==0) ? 0 : (t0-1);
    #pragma unroll 5
    for (int j = tref-(Kma-1); j <= tref; ++j) ws += xb[max(j,0)*Cdim];

    float tr_m1, tr_c, x_m1, x_c;
    if (seg == 0) {
        tr_c = ws*inv; tr_m1 = tr_c;
        x_c  = xb[0];  x_m1  = x_c;
    } else {
        tr_m1 = ws*inv;
        x_m1  = xb[(t0-1)*Cdim];
        ws   += xb[t0*Cdim] - xb[max(t0-Kma,0)*Cdim];
        tr_c  = ws*inv;
        x_c   = xb[t0*Cdim];
    }

    float Ssum = 0.f;
    #pragma unroll 4
    for (int t = t0; t < t1; ++t) {
        Ssum += tr_c;
        float tr_p, x_p;
        if (t+1 < Tdim) {
            x_p = xb[(t+1)*Cdim];
            ws += x_p - xb[max(t+1-Kma,0)*Cdim];
            tr_p = ws*inv;
        } else { x_p = x_c; tr_p = tr_c; }

        int m = b*Tdim + t;
        float tctx = fmaf(tr_m1,w0t, fmaf(tr_c,w1t, fmaf(tr_p,w2t, btc)));
        float xt = tanhf(tctx);
        float d2 = fmaf(2.f*xt, xt, -1.f);
        float d3 = xt * fmaf(4.f*xt, xt, -3.f);
        size_t arow = (size_t)m*(3*Cdim) + c;
        g_Ac16[arow]          = __float2half_rn(xt);
        g_Ac16[arow + Cdim]   = __float2half_rn(d2);
        g_Ac16[arow + 2*Cdim] = __float2half_rn(d3);

        float sm1 = x_m1-tr_m1, sc = x_c-tr_c, spp = x_p-tr_p;
        float sctx = fmaf(sm1,w0s, fmaf(sc,w1s, fmaf(spp,w2s, bsc)));
        g_sA16[(size_t)m*Cdim + c] = __float2half_rn(sctx);

        if (t == 0)      g_tr0[b*Cdim+c] = tr_c;
        if (t == Tdim-1) g_trN[b*Cdim+c] = tr_c;
        tr_m1 = tr_c; tr_c = tr_p; x_m1 = x_c; x_c = x_p;
    }
    g_Spart[seg][b*Cdim+c] = Ssum;
}

// ===================== K2: hypernetwork (3 stages) ==========================
__global__ void hyper_pool(const float* __restrict__ slw, const float* __restrict__ slb) {
    int b = blockIdx.x, c = threadIdx.x;   // 16 x 512
    float S = 0.f;
    #pragma unroll
    for (int s = 0; s < SEG; ++s) S += g_Spart[s][b*Cdim+c];
    float tr0 = g_tr0[b*Cdim+c], trN = g_trN[b*Cdim+c];
    float a0 = slw[c*3+0], a1 = slw[c*3+1], a2 = slw[c*3+2];
    float sp = (a0*(S + tr0 - trN) + a1*S + a2*(S - tr0 + trN)) * (1.0f/Tdim) + slb[c];
    g_h[b*2*Cdim + c]        = sp;
    g_h[b*2*Cdim + Cdim + c] = S * (1.0f/Tdim);
}

__global__ void hyper_mm(const float* __restrict__ w1, const float* __restrict__ b1) {
    int b = blockIdx.y;
    int col = blockIdx.x*128 + threadIdx.x;   // grid (4,16) x 128
    __shared__ float hs[2*Cdim];
    for (int i = threadIdx.x; i < 2*Cdim; i += 128) hs[i] = g_h[b*2*Cdim + i];
    __syncthreads();
    float a0=0.f, a1=0.f, a2=0.f, a3=0.f;
    #pragma unroll 4
    for (int i = 0; i < 2*Cdim; i += 4) {
        a0 = fmaf(hs[i+0], w1[(i+0)*Cdim + col], a0);
        a1 = fmaf(hs[i+1], w1[(i+1)*Cdim + col], a1);
        a2 = fmaf(hs[i+2], w1[(i+2)*Cdim + col], a2);
        a3 = fmaf(hs[i+3], w1[(i+3)*Cdim + col], a3);
    }
    float acc = ((a0+a1)+(a2+a3)) + b1[col];
    g_h1[b*Cdim + col] = acc / (1.f + expf(-acc));
}

__global__ void hyper_psi(const float* __restrict__ w2, const float* __restrict__ b2) {
    int b = blockIdx.x;
    int j = threadIdx.x;                      // 256
    int warp = j >> 5, lane = j & 31;
    __shared__ float params_s[2*NWv];
    if (warp < 2*NWv) {
        float v = 0.f;
        for (int jj = lane; jj < Cdim; jj += 32)
            v = fmaf(g_h1[b*Cdim + jj], w2[jj*(2*NWv) + warp], v);
        #pragma unroll
        for (int o = 16; o; o >>= 1) v += __shfl_down_sync(0xffffffffu, v, o);
        if (lane == 0) params_s[warp] = v + b2[warp];
    }
    __syncthreads();
    if (j < NWv) {
        float a = params_s[j*2+0], bb = params_s[j*2+1];
        g_wp[b*2*NWv + j*2 + 0] = ((a > 20.f) ? a : log1pf(expf(a))) + 0.01f;
        g_wp[b*2*NWv + j*2 + 1] = (float)Tdim / (1.f + expf(-bb));
    }
}

// ===================== fp16 mma GEMM (cp.async, 4 stages, 2 CTA/SM) =========
// mode 0: tout = Acheby @ Wc + bias0 (fp32) ; also tout fp16 -> g_Aa16
// mode 1: sout = (psi ⊗ sctx) @ Ww -> g_s16 fp16 (psi applied to A fragments)
// mode 2: amp  = 2*sigmoid(tout16 @ Wa + amp_b) -> g_a16 fp16
#define SPADH 40
#define TO_B  (128*SPADH*2)            // 10240 B
#define STG_BYTES (2*128*SPADH*2)      // 20480 B
#define NSTAGE 4
#define SMEM_GEMM (NSTAGE*STG_BYTES)   // 81920 B  (2 CTAs = 160KB <= 227KB)

__global__ __launch_bounds__(256, 2)
void gemm_kernel(int modeBase, const float* __restrict__ ampb) {
    int mode = modeBase + (int)blockIdx.z;
    const __half *Ag, *Bg; int Ktot;
    if (mode == 0)      { Ag = g_Ac16; Bg = g_Wc16; Ktot = 3*Cdim; }
    else if (mode == 1) { Ag = g_sA16; Bg = g_Ww16; Ktot = NWv*Cdim; }
    else                { Ag = g_Aa16; Bg = g_Wa16; Ktot = Cdim; }
    const int NKB = Ktot / 32;
    const int AK  = (mode == 1) ? Cdim : Ktot;   // A row length (wavelet wraps)

    extern __shared__ char smem[];
    uint32_t sbase = smem_u32(smem);
    int tid = threadIdx.x, lane = tid & 31, wid = tid >> 5;
    int wm = wid >> 2, wn = wid & 3;
    int m0 = blockIdx.y * 128, n0 = blockIdx.x * 128;

    int r = tid >> 1, hf_ = tid & 1;
    const __half* gA = Ag + (size_t)(m0 + r)*AK + hf_*16;
    const __half* gB = Bg + (size_t)(n0 + r)*Ktot + hf_*16;
    uint32_t sAd = sbase + (uint32_t)(r*SPADH + hf_*16)*2;
    uint32_t sBd = sAd + TO_B;

    auto issue = [&](int kb) {
        uint32_t so = (uint32_t)(kb & (NSTAGE-1))*STG_BYTES;
        int ak = (mode == 1) ? (kb & 15)*32 : kb*32;
        const __half* pa = gA + ak;
        const __half* pb = gB + (size_t)kb*32;
        cp16(sAd + so, pa); cp16(sAd + so + 16, pa + 8);
        cp16(sBd + so, pb); cp16(sBd + so + 16, pb + 8);
    };

    float acc[4][4][4];
    #pragma unroll
    for (int i = 0; i < 4; ++i)
        #pragma unroll
        for (int j = 0; j < 4; ++j)
            #pragma unroll
            for (int q = 0; q < 4; ++q) acc[i][j][q] = 0.f;

    uint32_t ph1[4], ph2[4];
    const int bIdx = m0 >> 10;
    const int tbase = m0 & (Tdim-1);

    const uint32_t aRowSel = lane & 15;
    const uint32_t aColSel = ((lane >> 4) & 1)*8;
    const uint32_t bRowSel = ((lane >> 4) & 1)*8 + (lane & 7);
    const uint32_t bColSel = ((lane >> 3) & 1)*8;

    const int NP = (NSTAGE-1 < NKB) ? NSTAGE-1 : NKB;
    for (int s = 0; s < NP; ++s) { issue(s); cp_commit(); }

    for (int kb = 0; kb < NKB; ++kb) {
        if (mode == 1 && (kb & 15) == 0) {
            int w = kb >> 4;
            float da = g_wp[bIdx*8 + w*2], dbv = g_wp[bIdx*8 + w*2 + 1];
            #pragma unroll
            for (int mt = 0; mt < 4; ++mt) {
                float t1 = (float)(tbase + wm*64 + mt*16 + (int)(lane >> 2));
                float z = (t1 - dbv)/da, z2 = z*z;
                float p1 = (1.f - z2)*expf(-0.5f*z2);
                float t2 = t1 + 8.f;
                z = (t2 - dbv)/da; z2 = z*z;
                float p2 = (1.f - z2)*expf(-0.5f*z2);
                __half2 h1v = __half2half2(__float2half_rn(p1));
                __half2 h2v = __half2half2(__float2half_rn(p2));
                ph1[mt] = *reinterpret_cast<uint32_t*>(&h1v);
                ph2[mt] = *reinterpret_cast<uint32_t*>(&h2v);
            }
        }
        cp_wait<NSTAGE-2>();
        __syncthreads();

        uint32_t sb = sbase + (uint32_t)(kb & (NSTAGE-1))*STG_BYTES;
        #pragma unroll
        for (int kk = 0; kk < 2; ++kk) {
            uint32_t kO = kk*16;
            uint32_t aF[4][4], bF[4][2];
            #pragma unroll
            for (int mt = 0; mt < 4; ++mt) {
                uint32_t row = wm*64 + mt*16 + aRowSel;
                ldmx4(sb + (row*SPADH + kO + aColSel)*2, aF[mt]);
            }
            if (mode == 1) {
                #pragma unroll
                for (int mt = 0; mt < 4; ++mt) {
                    aF[mt][0] = hmul2u(aF[mt][0], ph1[mt]);
                    aF[mt][2] = hmul2u(aF[mt][2], ph1[mt]);
                    aF[mt][1] = hmul2u(aF[mt][1], ph2[mt]);
                    aF[mt][3] = hmul2u(aF[mt][3], ph2[mt]);
                }
            }
            #pragma unroll
            for (int p = 0; p < 2; ++p) {
                uint32_t row = wn*32 + p*16 + bRowSel;
                uint32_t r4[4];
                ldmx4(sb + TO_B + (row*SPADH + kO + bColSel)*2, r4);
                bF[p*2+0][0] = r4[0]; bF[p*2+0][1] = r4[1];
                bF[p*2+1][0] = r4[2]; bF[p*2+1][1] = r4[3];
            }
            #pragma unroll
            for (int mt = 0; mt < 4; ++mt)
                #pragma unroll
                for (int nt = 0; nt < 4; ++nt)
                    mma16816(acc[mt][nt], aF[mt], bF[nt]);
        }
        if (kb + NSTAGE-1 < NKB) issue(kb + NSTAGE-1);
        cp_commit();
    }

    // ---- epilogue ----
    const int cRow = lane >> 2, cCol2 = (lane & 3)*2;
    #pragma unroll
    for (int mt = 0; mt < 4; ++mt) {
        #pragma unroll
        for (int nt = 0; nt < 4; ++nt) {
            int col = n0 + wn*32 + nt*8 + cCol2;
            float v0 = acc[mt][nt][0], v1 = acc[mt][nt][1];
            float v2 = acc[mt][nt][2], v3 = acc[mt][nt][3];
            int row = m0 + wm*64 + mt*16 + cRow;
            if (mode == 0) {
                float b0 = g_bias0[col], b1 = g_bias0[col+1];
                v0 += b0; v1 += b1; v2 += b0; v3 += b1;
                *reinterpret_cast<__half2*>(&g_Aa16[(size_t)row*Cdim + col]) =
                    __floats2half2_rn(v0, v1);
                *reinterpret_cast<__half2*>(&g_Aa16[(size_t)(row+8)*Cdim + col]) =
                    __floats2half2_rn(v2, v3);
                *reinterpret_cast<float2*>(g_tout + (size_t)row*Cdim + col)     = make_float2(v0, v1);
                *reinterpret_cast<float2*>(g_tout + (size_t)(row+8)*Cdim + col) = make_float2(v2, v3);
            } else if (mode == 1) {
                *reinterpret_cast<__half2*>(&g_s16[(size_t)row*Cdim + col]) =
                    __floats2half2_rn(v0, v1);
                *reinterpret_cast<__half2*>(&g_s16[(size_t)(row+8)*Cdim + col]) =
                    __floats2half2_rn(v2, v3);
            } else {
                float b0 = ampb[col], b1 = ampb[col+1];
                v0 = 2.f/(1.f+expf(-(v0+b0))); v1 = 2.f/(1.f+expf(-(v1+b1)));
                v2 = 2.f/(1.f+expf(-(v2+b0))); v3 = 2.f/(1.f+expf(-(v3+b1)));
                *reinterpret_cast<__half2*>(&g_a16[(size_t)row*Cdim + col]) =
                    __floats2half2_rn(v0, v1);
                *reinterpret_cast<__half2*>(&g_a16[(size_t)(row+8)*Cdim + col]) =
                    __floats2half2_rn(v2, v3);
            }
        }
    }
}

// ===================== K5: gate + residual + LayerNorm ======================
__global__ void epilogue_kernel(const float* __restrict__ x,
                                const float* __restrict__ gamma,
                                const float* __restrict__ beta,
                                float* __restrict__ out) {
    int m = blockIdx.x;
    int i = threadIdx.x;            // 128 threads, 4 floats each
    size_t bse = (size_t)m*Cdim + i*4;
    float4 to = *reinterpret_cast<const float4*>(&g_tout[bse]);
    float4 xv = *reinterpret_cast<const float4*>(&x[bse]);
    uint2 su = *reinterpret_cast<const uint2*>(&g_s16[bse]);
    uint2 au = *reinterpret_cast<const uint2*>(&g_a16[bse]);
    float2 s0 = __half22float2(*reinterpret_cast<__half2*>(&su.x));
    float2 s1 = __half22float2(*reinterpret_cast<__half2*>(&su.y));
    float2 a0 = __half22float2(*reinterpret_cast<__half2*>(&au.x));
    float2 a1 = __half22float2(*reinterpret_cast<__half2*>(&au.y));
    float4 y;
    y.x = fmaf(s0.x, a0.x, to.x) + xv.x;
    y.y = fmaf(s0.y, a0.y, to.y) + xv.y;
    y.z = fmaf(s1.x, a1.x, to.z) + xv.z;
    y.w = fmaf(s1.y, a1.y, to.w) + xv.w;

    float s  = y.x + y.y + y.z + y.w;
    float sq = y.x*y.x + y.y*y.y + y.z*y.z + y.w*y.w;
    #pragma unroll
    for (int o = 16; o; o >>= 1) {
        s  += __shfl_down_sync(0xffffffffu, s,  o);
        sq += __shfl_down_sync(0xffffffffu, sq, o);
    }
    __shared__ float rs[4], rq[4];
    int warp = i >> 5, lane = i & 31;
    if (lane == 0) { rs[warp] = s; rq[warp] = sq; }
    __syncthreads();
    float ts = rs[0]+rs[1]+rs[2]+rs[3];
    float tq = rq[0]+rq[1]+rq[2]+rq[3];
    float mu  = ts * (1.0f/Cdim);
    float var = tq * (1.0f/Cdim) - mu*mu;
    float r = rsqrtf(var + 1e-5f);

    float4 g = *reinterpret_cast<const float4*>(&gamma[i*4]);
    float4 bb= *reinterpret_cast<const float4*>(&beta[i*4]);
    float4 o4;
    o4.x = (y.x-mu)*r*g.x + bb.x;
    o4.y = (y.y-mu)*r*g.y + bb.y;
    o4.z = (y.z-mu)*r*g.z + bb.z;
    o4.w = (y.w-mu)*r*g.w + bb.w;
    *reinterpret_cast<float4*>(&out[bse]) = o4;
}

// ===================== launch ===============================================
extern "C" void kernel_launch(void* const* d_in, const int* in_sizes, int n_in,
                              void* d_out, int out_size) {
    const float* x     = (const float*)d_in[0];
    const float* tw    = (const float*)d_in[1];
    const float* tb    = (const float*)d_in[2];
    const float* sw    = (const float*)d_in[3];
    const float* sb    = (const float*)d_in[4];
    const float* slw   = (const float*)d_in[5];
    const float* slb   = (const float*)d_in[6];
    const float* cheby = (const float*)d_in[7];
    const float* hw1   = (const float*)d_in[8];
    const float* hb1   = (const float*)d_in[9];
    const float* hw2   = (const float*)d_in[10];
    const float* hb2   = (const float*)d_in[11];
    const float* amp_w = (const float*)d_in[12];
    const float* amp_b = (const float*)d_in[13];
    const float* wav_w = (const float*)d_in[14];
    const float* gamma = (const float*)d_in[15];
    const float* beta  = (const float*)d_in[16];
    float* out = (float*)d_out;

    cudaFuncSetAttribute(gemm_kernel, cudaFuncAttributeMaxDynamicSharedMemorySize, SMEM_GEMM);

    prep_all<<<2049, 256>>>(cheby, wav_w, amp_w);
    decomp_kernel<<<(SEG*Bdim*Cdim)/256, 256>>>(x, tw, tb, sw, sb);
    hyper_pool<<<Bdim, 512>>>(slw, slb);
    hyper_mm<<<dim3(4, Bdim), 128>>>(hw1, hb1);
    hyper_psi<<<Bdim, 256>>>(hw2, hb2);

    gemm_kernel<<<dim3(4, Mrows/128, 2), 256, SMEM_GEMM>>>(0, nullptr);  // cheby + wavelet
    gemm_kernel<<<dim3(4, Mrows/128, 1), 256, SMEM_GEMM>>>(2, amp_b);    // amp gate

    epilogue_kernel<<<Mrows, 128>>>(x, gamma, beta, out);
}

// round 6
// speedup vs baseline: 4.2230x; 1.1042x over previous
#include <cuda_runtime.h>
#include <cuda_fp16.h>
#include <cstdint>
#include <math.h>

#define Bdim 16
#define Tdim 1024
#define Cdim 512
#define Kma  25
#define NWv  4
#define Mrows (Bdim*Tdim)   // 16384
#define SEG  8
#define SEGLEN (Tdim/SEG)   // 128

// ===================== scratch ==============================================
__device__ __half g_Ac16[Mrows*3*Cdim];   // cheby basis A, [m][k=(d-1)*512+c]
__device__ __half g_sA16[Mrows*Cdim];     // spike_ctx fp16 (wavelet A base)
__device__ __half g_Aa16[Mrows*Cdim];     // tout fp16 (amp A + epilogue trend)
__device__ __half g_s16 [Mrows*Cdim];     // spike_out fp16
__device__ __half g_a16 [Mrows*Cdim];     // amp_scale fp16
__device__ float  g_bias0[Cdim];
__device__ float  g_Spart[SEG][Bdim*Cdim];
__device__ float  g_tr0[Bdim*Cdim];
__device__ float  g_trN[Bdim*Cdim];
__device__ float  g_h  [Bdim*2*Cdim];
__device__ float  g_hacc[Bdim*Cdim];      // pre-activation h1 accumulator
__device__ float  g_wp [Bdim*2*NWv];      // [b][w*2 + {0:da,1:db}]
// weights transposed to [o][k], fp16
__device__ __half g_Wc16[Cdim*3*Cdim];
__device__ __half g_Ww16[Cdim*NWv*Cdim];
__device__ __half g_Wa16[Cdim*Cdim];

// ===================== helpers ==============================================
__device__ __forceinline__ uint32_t smem_u32(const void* p) {
    uint32_t a;
    asm("{ .reg .u64 t; cvta.to.shared.u64 t, %1; cvt.u32.u64 %0, t; }" : "=r"(a) : "l"(p));
    return a;
}
__device__ __forceinline__ void cp16(uint32_t dst, const void* src) {
    asm volatile("cp.async.cg.shared.global [%0], [%1], 16;" :: "r"(dst), "l"(src));
}
__device__ __forceinline__ void cp_commit() { asm volatile("cp.async.commit_group;"); }
template<int N> __device__ __forceinline__ void cp_wait() {
    asm volatile("cp.async.wait_group %0;" :: "n"(N));
}
__device__ __forceinline__ void ldmx4(uint32_t addr, uint32_t* r) {
    asm volatile("ldmatrix.sync.aligned.m8n8.x4.shared.b16 {%0,%1,%2,%3}, [%4];"
        : "=r"(r[0]), "=r"(r[1]), "=r"(r[2]), "=r"(r[3]) : "r"(addr));
}
__device__ __forceinline__ void mma16816(float* c, const uint32_t* a, const uint32_t* b) {
    asm volatile("mma.sync.aligned.m16n8k16.row.col.f32.f16.f16.f32 "
        "{%0,%1,%2,%3}, {%4,%5,%6,%7}, {%8,%9}, {%0,%1,%2,%3};"
        : "+f"(c[0]), "+f"(c[1]), "+f"(c[2]), "+f"(c[3])
        : "r"(a[0]), "r"(a[1]), "r"(a[2]), "r"(a[3]), "r"(b[0]), "r"(b[1]));
}
__device__ __forceinline__ uint32_t hmul2u(uint32_t a, uint32_t b) {
    __half2 r = __hmul2(*reinterpret_cast<__half2*>(&a), *reinterpret_cast<__half2*>(&b));
    return *reinterpret_cast<uint32_t*>(&r);
}

// ===================== K0: fused weight prep (all 4 jobs) ===================
__global__ void prep_all(const float* __restrict__ cheby,
                         const float* __restrict__ wav_w,
                         const float* __restrict__ amp_w) {
    int bx = blockIdx.x;
    int tx = threadIdx.x & 31, ty = threadIdx.x >> 5;   // 32 x 8

    if (bx == 2048) {
        for (int o = threadIdx.x; o < Cdim; o += 256) {
            float s = 0.f;
            for (int c = 0; c < Cdim; ++c) s += cheby[(c*Cdim + o)*4];
            g_bias0[o] = s;
        }
        return;
    }

    const float* src; __half* dst; int Ktot, kb, ob, mode;
    if (bx < 768)       { mode = 0; src = cheby; dst = g_Wc16; Ktot = 3*Cdim;
                          kb = (bx % 48)*32;  ob = (bx / 48)*32; }
    else if (bx < 1792) { mode = 1; src = wav_w; dst = g_Ww16; Ktot = NWv*Cdim;
                          int i = bx - 768;  kb = (i % 64)*32; ob = (i / 64)*32; }
    else                { mode = 2; src = amp_w; dst = g_Wa16; Ktot = Cdim;
                          int i = bx - 1792; kb = (i % 16)*32; ob = (i / 16)*32; }

    __shared__ float tile[32][33];
    #pragma unroll
    for (int s = 0; s < 32; s += 8) {
        int k = kb + ty + s, o = ob + tx;
        float v;
        if (mode == 0) { int d = k >> 9, c = k & 511; v = src[(c*Cdim + o)*4 + d + 1]; }
        else           { v = src[(size_t)k*Cdim + o]; }
        tile[ty+s][tx] = v;
    }
    __syncthreads();
    #pragma unroll
    for (int s = 0; s < 32; s += 8) {
        int o = ob + ty + s, k = kb + tx;
        dst[(size_t)o*Ktot + k] = __float2half_rn(tile[tx][ty+s]);
    }
}

// ===================== K1: fused decomposition ==============================
__global__ void decomp_kernel(const float* __restrict__ x,
                              const float* __restrict__ tw, const float* __restrict__ tb,
                              const float* __restrict__ sw, const float* __restrict__ sb) {
    int idx = blockIdx.x*blockDim.x + threadIdx.x;
    int c   = idx & (Cdim-1);
    int tmp = idx >> 9;
    int b   = tmp & (Bdim-1);
    int seg = tmp >> 4;
    const float* xb = x + (size_t)b*Tdim*Cdim + c;
    const float inv = 1.0f/(float)Kma;
    float w0t=tw[c*3+0], w1t=tw[c*3+1], w2t=tw[c*3+2], btc=tb[c];
    float w0s=sw[c*3+0], w1s=sw[c*3+1], w2s=sw[c*3+2], bsc=sb[c];

    int t0 = seg*SEGLEN, t1 = t0 + SEGLEN;
    float ws = 0.f;
    int tref = (seg==0) ? 0 : (t0-1);
    #pragma unroll 5
    for (int j = tref-(Kma-1); j <= tref; ++j) ws += xb[max(j,0)*Cdim];

    float tr_m1, tr_c, x_m1, x_c;
    if (seg == 0) {
        tr_c = ws*inv; tr_m1 = tr_c;
        x_c  = xb[0];  x_m1  = x_c;
    } else {
        tr_m1 = ws*inv;
        x_m1  = xb[(t0-1)*Cdim];
        ws   += xb[t0*Cdim] - xb[max(t0-Kma,0)*Cdim];
        tr_c  = ws*inv;
        x_c   = xb[t0*Cdim];
    }

    float Ssum = 0.f;
    #pragma unroll 4
    for (int t = t0; t < t1; ++t) {
        Ssum += tr_c;
        float tr_p, x_p;
        if (t+1 < Tdim) {
            x_p = xb[(t+1)*Cdim];
            ws += x_p - xb[max(t+1-Kma,0)*Cdim];
            tr_p = ws*inv;
        } else { x_p = x_c; tr_p = tr_c; }

        int m = b*Tdim + t;
        float tctx = fmaf(tr_m1,w0t, fmaf(tr_c,w1t, fmaf(tr_p,w2t, btc)));
        float xt = tanhf(tctx);
        float d2 = fmaf(2.f*xt, xt, -1.f);
        float d3 = xt * fmaf(4.f*xt, xt, -3.f);
        size_t arow = (size_t)m*(3*Cdim) + c;
        g_Ac16[arow]          = __float2half_rn(xt);
        g_Ac16[arow + Cdim]   = __float2half_rn(d2);
        g_Ac16[arow + 2*Cdim] = __float2half_rn(d3);

        float sm1 = x_m1-tr_m1, sc = x_c-tr_c, spp = x_p-tr_p;
        float sctx = fmaf(sm1,w0s, fmaf(sc,w1s, fmaf(spp,w2s, bsc)));
        g_sA16[(size_t)m*Cdim + c] = __float2half_rn(sctx);

        if (t == 0)      g_tr0[b*Cdim+c] = tr_c;
        if (t == Tdim-1) g_trN[b*Cdim+c] = tr_c;
        tr_m1 = tr_c; tr_c = tr_p; x_m1 = x_c; x_c = x_p;
    }
    g_Spart[seg][b*Cdim+c] = Ssum;
}

// ===================== K2: hypernetwork (3 stages) ==========================
__global__ void hyper_pool(const float* __restrict__ slw, const float* __restrict__ slb) {
    int b = blockIdx.x, c = threadIdx.x;   // 16 x 512
    g_hacc[b*Cdim + c] = 0.f;              // zero the split-K accumulator
    float S = 0.f;
    #pragma unroll
    for (int s = 0; s < SEG; ++s) S += g_Spart[s][b*Cdim+c];
    float tr0 = g_tr0[b*Cdim+c], trN = g_trN[b*Cdim+c];
    float a0 = slw[c*3+0], a1 = slw[c*3+1], a2 = slw[c*3+2];
    float sp = (a0*(S + tr0 - trN) + a1*S + a2*(S - tr0 + trN)) * (1.0f/Tdim) + slb[c];
    g_h[b*2*Cdim + c]        = sp;
    g_h[b*2*Cdim + Cdim + c] = S * (1.0f/Tdim);
}

// split-K: grid (4, 16, 8) x 256; block (cx,b,ks) does k in [ks*128, ks*128+128)
__global__ void hyper_mm(const float* __restrict__ w1) {
    int b = blockIdx.y, ks = blockIdx.z;
    int col = blockIdx.x*128 + (threadIdx.x & 127);
    int kh  = threadIdx.x >> 7;          // 0/1 -> 64-k half
    __shared__ float hs[128];
    if (threadIdx.x < 128) hs[threadIdx.x] = g_h[b*2*Cdim + ks*128 + threadIdx.x];
    __syncthreads();
    const float* wp = w1 + (size_t)(ks*128 + kh*64)*Cdim + col;
    const float* hp = hs + kh*64;
    float a0=0.f, a1=0.f, a2=0.f, a3=0.f;
    #pragma unroll 4
    for (int i = 0; i < 64; i += 4) {
        a0 = fmaf(hp[i+0], wp[(i+0)*Cdim], a0);
        a1 = fmaf(hp[i+1], wp[(i+1)*Cdim], a1);
        a2 = fmaf(hp[i+2], wp[(i+2)*Cdim], a2);
        a3 = fmaf(hp[i+3], wp[(i+3)*Cdim], a3);
    }
    atomicAdd(&g_hacc[b*Cdim + col], (a0+a1)+(a2+a3));
}

__global__ void hyper_psi(const float* __restrict__ w2, const float* __restrict__ b2,
                          const float* __restrict__ b1) {
    int b = blockIdx.x;
    int j = threadIdx.x;                      // 256
    int warp = j >> 5, lane = j & 31;
    __shared__ float params_s[2*NWv];
    if (warp < 2*NWv) {
        float v = 0.f;
        for (int jj = lane; jj < Cdim; jj += 32) {
            float hv = g_hacc[b*Cdim + jj] + b1[jj];
            hv = hv / (1.f + expf(-hv));      // silu
            v = fmaf(hv, w2[jj*(2*NWv) + warp], v);
        }
        #pragma unroll
        for (int o = 16; o; o >>= 1) v += __shfl_down_sync(0xffffffffu, v, o);
        if (lane == 0) params_s[warp] = v + b2[warp];
    }
    __syncthreads();
    if (j < NWv) {
        float a = params_s[j*2+0], bb = params_s[j*2+1];
        g_wp[b*2*NWv + j*2 + 0] = ((a > 20.f) ? a : log1pf(expf(a))) + 0.01f;
        g_wp[b*2*NWv + j*2 + 1] = (float)Tdim / (1.f + expf(-bb));
    }
}

// ===================== fp16 mma GEMM (cp.async, 4 stages, 2 CTA/SM) =========
// mode 0: tout16 = Acheby @ Wc + bias0 -> g_Aa16
// mode 1: sout   = (psi ⊗ sctx) @ Ww   -> g_s16 (psi applied to A fragments)
// mode 2: amp    = 2*sigmoid(tout16 @ Wa + amp_b) -> g_a16
#define SPADH 40
#define TO_B  (128*SPADH*2)            // 10240 B
#define STG_BYTES (2*128*SPADH*2)      // 20480 B
#define NSTAGE 4
#define SMEM_GEMM (NSTAGE*STG_BYTES)   // 81920 B  (2 CTAs = 160KB)

__global__ __launch_bounds__(256, 2)
void gemm_kernel(int modeBase, const float* __restrict__ ampb) {
    int mode = modeBase + (int)blockIdx.z;
    const __half *Ag, *Bg; int Ktot;
    if (mode == 0)      { Ag = g_Ac16; Bg = g_Wc16; Ktot = 3*Cdim; }
    else if (mode == 1) { Ag = g_sA16; Bg = g_Ww16; Ktot = NWv*Cdim; }
    else                { Ag = g_Aa16; Bg = g_Wa16; Ktot = Cdim; }
    const int NKB = Ktot / 32;
    const int AK  = (mode == 1) ? Cdim : Ktot;   // A row length (wavelet wraps)

    extern __shared__ char smem[];
    uint32_t sbase = smem_u32(smem);
    int tid = threadIdx.x, lane = tid & 31, wid = tid >> 5;
    int wm = wid >> 2, wn = wid & 3;
    int m0 = blockIdx.y * 128, n0 = blockIdx.x * 128;

    int r = tid >> 1, hf_ = tid & 1;
    const __half* gA = Ag + (size_t)(m0 + r)*AK + hf_*16;
    const __half* gB = Bg + (size_t)(n0 + r)*Ktot + hf_*16;
    uint32_t sAd = sbase + (uint32_t)(r*SPADH + hf_*16)*2;
    uint32_t sBd = sAd + TO_B;

    auto issue = [&](int kb) {
        uint32_t so = (uint32_t)(kb & (NSTAGE-1))*STG_BYTES;
        int ak = (mode == 1) ? (kb & 15)*32 : kb*32;
        const __half* pa = gA + ak;
        const __half* pb = gB + (size_t)kb*32;
        cp16(sAd + so, pa); cp16(sAd + so + 16, pa + 8);
        cp16(sBd + so, pb); cp16(sBd + so + 16, pb + 8);
    };

    float acc[4][4][4];
    #pragma unroll
    for (int i = 0; i < 4; ++i)
        #pragma unroll
        for (int j = 0; j < 4; ++j)
            #pragma unroll
            for (int q = 0; q < 4; ++q) acc[i][j][q] = 0.f;

    uint32_t ph1[4], ph2[4];
    const int bIdx = m0 >> 10;
    const int tbase = m0 & (Tdim-1);

    const uint32_t aRowSel = lane & 15;
    const uint32_t aColSel = ((lane >> 4) & 1)*8;
    const uint32_t bRowSel = ((lane >> 4) & 1)*8 + (lane & 7);
    const uint32_t bColSel = ((lane >> 3) & 1)*8;

    const int NP = (NSTAGE-1 < NKB) ? NSTAGE-1 : NKB;
    for (int s = 0; s < NP; ++s) { issue(s); cp_commit(); }

    for (int kb = 0; kb < NKB; ++kb) {
        if (mode == 1 && (kb & 15) == 0) {
            int w = kb >> 4;
            float da = g_wp[bIdx*8 + w*2], dbv = g_wp[bIdx*8 + w*2 + 1];
            #pragma unroll
            for (int mt = 0; mt < 4; ++mt) {
                float t1 = (float)(tbase + wm*64 + mt*16 + (int)(lane >> 2));
                float z = (t1 - dbv)/da, z2 = z*z;
                float p1 = (1.f - z2)*expf(-0.5f*z2);
                float t2 = t1 + 8.f;
                z = (t2 - dbv)/da; z2 = z*z;
                float p2 = (1.f - z2)*expf(-0.5f*z2);
                __half2 h1v = __half2half2(__float2half_rn(p1));
                __half2 h2v = __half2half2(__float2half_rn(p2));
                ph1[mt] = *reinterpret_cast<uint32_t*>(&h1v);
                ph2[mt] = *reinterpret_cast<uint32_t*>(&h2v);
            }
        }
        cp_wait<NSTAGE-2>();
        __syncthreads();

        uint32_t sb = sbase + (uint32_t)(kb & (NSTAGE-1))*STG_BYTES;
        #pragma unroll
        for (int kk = 0; kk < 2; ++kk) {
            uint32_t kO = kk*16;
            uint32_t aF[4][4], bF[4][2];
            #pragma unroll
            for (int mt = 0; mt < 4; ++mt) {
                uint32_t row = wm*64 + mt*16 + aRowSel;
                ldmx4(sb + (row*SPADH + kO + aColSel)*2, aF[mt]);
            }
            if (mode == 1) {
                #pragma unroll
                for (int mt = 0; mt < 4; ++mt) {
                    aF[mt][0] = hmul2u(aF[mt][0], ph1[mt]);
                    aF[mt][2] = hmul2u(aF[mt][2], ph1[mt]);
                    aF[mt][1] = hmul2u(aF[mt][1], ph2[mt]);
                    aF[mt][3] = hmul2u(aF[mt][3], ph2[mt]);
                }
            }
            #pragma unroll
            for (int p = 0; p < 2; ++p) {
                uint32_t row = wn*32 + p*16 + bRowSel;
                uint32_t r4[4];
                ldmx4(sb + TO_B + (row*SPADH + kO + bColSel)*2, r4);
                bF[p*2+0][0] = r4[0]; bF[p*2+0][1] = r4[1];
                bF[p*2+1][0] = r4[2]; bF[p*2+1][1] = r4[3];
            }
            #pragma unroll
            for (int mt = 0; mt < 4; ++mt)
                #pragma unroll
                for (int nt = 0; nt < 4; ++nt)
                    mma16816(acc[mt][nt], aF[mt], bF[nt]);
        }
        if (kb + NSTAGE-1 < NKB) issue(kb + NSTAGE-1);
        cp_commit();
    }

    // ---- epilogue ----
    const int cRow = lane >> 2, cCol2 = (lane & 3)*2;
    #pragma unroll
    for (int mt = 0; mt < 4; ++mt) {
        #pragma unroll
        for (int nt = 0; nt < 4; ++nt) {
            int col = n0 + wn*32 + nt*8 + cCol2;
            float v0 = acc[mt][nt][0], v1 = acc[mt][nt][1];
            float v2 = acc[mt][nt][2], v3 = acc[mt][nt][3];
            int row = m0 + wm*64 + mt*16 + cRow;
            if (mode == 0) {
                float b0 = g_bias0[col], b1 = g_bias0[col+1];
                v0 += b0; v1 += b1; v2 += b0; v3 += b1;
                *reinterpret_cast<__half2*>(&g_Aa16[(size_t)row*Cdim + col]) =
                    __floats2half2_rn(v0, v1);
                *reinterpret_cast<__half2*>(&g_Aa16[(size_t)(row+8)*Cdim + col]) =
                    __floats2half2_rn(v2, v3);
            } else if (mode == 1) {
                *reinterpret_cast<__half2*>(&g_s16[(size_t)row*Cdim + col]) =
                    __floats2half2_rn(v0, v1);
                *reinterpret_cast<__half2*>(&g_s16[(size_t)(row+8)*Cdim + col]) =
                    __floats2half2_rn(v2, v3);
            } else {
                float b0 = ampb[col], b1 = ampb[col+1];
                v0 = 2.f/(1.f+expf(-(v0+b0))); v1 = 2.f/(1.f+expf(-(v1+b1)));
                v2 = 2.f/(1.f+expf(-(v2+b0))); v3 = 2.f/(1.f+expf(-(v3+b1)));
                *reinterpret_cast<__half2*>(&g_a16[(size_t)row*Cdim + col]) =
                    __floats2half2_rn(v0, v1);
                *reinterpret_cast<__half2*>(&g_a16[(size_t)(row+8)*Cdim + col]) =
                    __floats2half2_rn(v2, v3);
            }
        }
    }
}

// ===================== K5: gate + residual + LayerNorm ======================
__global__ void epilogue_kernel(const float* __restrict__ x,
                                const float* __restrict__ gamma,
                                const float* __restrict__ beta,
                                float* __restrict__ out) {
    int m = blockIdx.x;
    int i = threadIdx.x;            // 128 threads, 4 elems each
    size_t bse = (size_t)m*Cdim + i*4;
    float4 xv = *reinterpret_cast<const float4*>(&x[bse]);
    uint2 tu = *reinterpret_cast<const uint2*>(&g_Aa16[bse]);
    uint2 su = *reinterpret_cast<const uint2*>(&g_s16[bse]);
    uint2 au = *reinterpret_cast<const uint2*>(&g_a16[bse]);
    float2 t0 = __half22float2(*reinterpret_cast<__half2*>(&tu.x));
    float2 t1 = __half22float2(*reinterpret_cast<__half2*>(&tu.y));
    float2 s0 = __half22float2(*reinterpret_cast<__half2*>(&su.x));
    float2 s1 = __half22float2(*reinterpret_cast<__half2*>(&su.y));
    float2 a0 = __half22float2(*reinterpret_cast<__half2*>(&au.x));
    float2 a1 = __half22float2(*reinterpret_cast<__half2*>(&au.y));
    float4 y;
    y.x = fmaf(s0.x, a0.x, t0.x) + xv.x;
    y.y = fmaf(s0.y, a0.y, t0.y) + xv.y;
    y.z = fmaf(s1.x, a1.x, t1.x) + xv.z;
    y.w = fmaf(s1.y, a1.y, t1.y) + xv.w;

    float s  = y.x + y.y + y.z + y.w;
    float sq = y.x*y.x + y.y*y.y + y.z*y.z + y.w*y.w;
    #pragma unroll
    for (int o = 16; o; o >>= 1) {
        s  += __shfl_down_sync(0xffffffffu, s,  o);
        sq += __shfl_down_sync(0xffffffffu, sq, o);
    }
    __shared__ float rs[4], rq[4];
    int warp = i >> 5, lane = i & 31;
    if (lane == 0) { rs[warp] = s; rq[warp] = sq; }
    __syncthreads();
    float ts = rs[0]+rs[1]+rs[2]+rs[3];
    float tq = rq[0]+rq[1]+rq[2]+rq[3];
    float mu  = ts * (1.0f/Cdim);
    float var = tq * (1.0f/Cdim) - mu*mu;
    float r = rsqrtf(var + 1e-5f);

    float4 g = *reinterpret_cast<const float4*>(&gamma[i*4]);
    float4 bb= *reinterpret_cast<const float4*>(&beta[i*4]);
    float4 o4;
    o4.x = (y.x-mu)*r*g.x + bb.x;
    o4.y = (y.y-mu)*r*g.y + bb.y;
    o4.z = (y.z-mu)*r*g.z + bb.z;
    o4.w = (y.w-mu)*r*g.w + bb.w;
    *reinterpret_cast<float4*>(&out[bse]) = o4;
}

// ===================== launch ===============================================
extern "C" void kernel_launch(void* const* d_in, const int* in_sizes, int n_in,
                              void* d_out, int out_size) {
    const float* x     = (const float*)d_in[0];
    const float* tw    = (const float*)d_in[1];
    const float* tb    = (const float*)d_in[2];
    const float* sw    = (const float*)d_in[3];
    const float* sb    = (const float*)d_in[4];
    const float* slw   = (const float*)d_in[5];
    const float* slb   = (const float*)d_in[6];
    const float* cheby = (const float*)d_in[7];
    const float* hw1   = (const float*)d_in[8];
    const float* hb1   = (const float*)d_in[9];
    const float* hw2   = (const float*)d_in[10];
    const float* hb2   = (const float*)d_in[11];
    const float* amp_w = (const float*)d_in[12];
    const float* amp_b = (const float*)d_in[13];
    const float* wav_w = (const float*)d_in[14];
    const float* gamma = (const float*)d_in[15];
    const float* beta  = (const float*)d_in[16];
    float* out = (float*)d_out;

    cudaFuncSetAttribute(gemm_kernel, cudaFuncAttributeMaxDynamicSharedMemorySize, SMEM_GEMM);

    prep_all<<<2049, 256>>>(cheby, wav_w, amp_w);
    decomp_kernel<<<(SEG*Bdim*Cdim)/256, 256>>>(x, tw, tb, sw, sb);
    hyper_pool<<<Bdim, 512>>>(slw, slb);
    hyper_mm<<<dim3(4, Bdim, 8), 256>>>(hw1);
    hyper_psi<<<Bdim, 256>>>(hw2, hb2, hb1);

    gemm_kernel<<<dim3(4, Mrows/128, 2), 256, SMEM_GEMM>>>(0, nullptr);  // cheby + wavelet
    gemm_kernel<<<dim3(4, Mrows/128, 1), 256, SMEM_GEMM>>>(2, amp_b);    // amp gate

    epilogue_kernel<<<Mrows, 128>>>(x, gamma, beta, out);
}